// round 2
// baseline (speedup 1.0000x reference)
#include <cuda_runtime.h>
#include <cuda_bf16.h>
#include <math.h>

// ---------------- f32x2 packed-math helpers ----------------
__device__ __forceinline__ unsigned long long splat2(float v) {
    unsigned long long r;
    unsigned u = __float_as_uint(v);
    asm("mov.b64 %0, {%1, %1};" : "=l"(r) : "r"(u));
    return r;
}
__device__ __forceinline__ unsigned long long pack2(float a, float b) {
    unsigned long long r;
    asm("mov.b64 %0, {%1, %2};" : "=l"(r)
        : "r"(__float_as_uint(a)), "r"(__float_as_uint(b)));
    return r;
}
__device__ __forceinline__ void fma2(unsigned long long& d,
                                     unsigned long long a, unsigned long long b) {
    asm("fma.rn.f32x2 %0, %1, %2, %0;" : "+l"(d) : "l"(a), "l"(b));
}
__device__ __forceinline__ float2 unpk(unsigned long long p) {
    unsigned lo, hi;
    asm("mov.b64 {%0, %1}, %2;" : "=r"(lo), "=r"(hi) : "l"(p));
    return make_float2(__uint_as_float(lo), __uint_as_float(hi));
}

// ---------------- scratch ----------------
__device__ float g_buf1[64 * 64 * 64 * 64];
__device__ float g_buf2[64 * 128 * 32 * 32];
__device__ float g_buf3[64 * 128 * 32 * 32];
__device__ float g_buf4[64 * 64 * 32 * 32];
__device__ float g_buf5[64 * 64 * 32 * 32];
__device__ float g_counts[512];
__device__ float g_loss[1];

// ---------------- tiled direct conv, 8co x 8px per thread, f32x2 ----------------
// block = 128 threads covering a 32x32 output tile for 8 output channels.
template <int K, int S, int CIN>
__global__ void __launch_bounds__(128) conv_tiled8(
    const float* __restrict__ in, const float* __restrict__ w,
    const float* __restrict__ bias, const float* __restrict__ resid,
    float* __restrict__ out, int Cout, int Hin, int Win, int Hout, int Wout,
    int in_relu, int out_relu)
{
    constexpr int P = 1;
    constexpr int TI = 31 * S + K;
    constexpr int TIP = (TI + 3) & ~3;
    constexpr int WN = CIN * K * K;
    extern __shared__ float smem[];
    float* wsm = smem;                 // WN * 8 floats
    float* tile = smem + WN * 8;       // TI rows x TIP stride

    const int tid = threadIdx.x;
    const int co0 = blockIdx.x * 8;
    const int n = blockIdx.y;
    const int tilesX = Wout >> 5;
    const int ty = blockIdx.z / tilesX, tx = blockIdx.z % tilesX;
    const int r0 = ty * 32, c0 = tx * 32;

    for (int j = tid; j < WN; j += 128) {
#pragma unroll
        for (int c = 0; c < 8; c++)
            wsm[j * 8 + c] = w[(size_t)(co0 + c) * WN + j];
    }

    const int row = tid >> 2;
    const int col8 = (tid & 3) << 3;

    unsigned long long acc[8][4];
#pragma unroll
    for (int a = 0; a < 8; a++)
#pragma unroll
        for (int b = 0; b < 4; b++) acc[a][b] = 0ull;

    const float* inb = in + (size_t)n * CIN * Hin * Win;

    for (int ci = 0; ci < CIN; ci++) {
        __syncthreads();
        const float* ip = inb + (size_t)ci * Hin * Win;
        for (int i = tid; i < TI * TI; i += 128) {
            int tr = i / TI, tc = i - tr * TI;
            int gr = r0 * S - P + tr, gc = c0 * S - P + tc;
            float v = 0.f;
            if (gr >= 0 && gr < Hin && gc >= 0 && gc < Win) v = ip[gr * Win + gc];
            if (in_relu) v = fmaxf(v, 0.f);
            tile[tr * TIP + tc] = v;
        }
        __syncthreads();

        constexpr int RW = (7 * S + K + 3) & ~3;
#pragma unroll
        for (int kh = 0; kh < K; kh++) {
            float rg[RW];
            const float4* rp = (const float4*)(tile + (row * S + kh) * TIP + col8 * S);
#pragma unroll
            for (int q = 0; q < RW / 4; q++) *(float4*)&rg[q * 4] = rp[q];
#pragma unroll
            for (int kw = 0; kw < K; kw++) {
                const ulonglong2* wp =
                    (const ulonglong2*)(wsm + ((ci * K + kh) * K + kw) * 8);
                ulonglong2 wA = wp[0], wB = wp[1];
#pragma unroll
                for (int px = 0; px < 8; px++) {
                    unsigned long long ipk = splat2(rg[px * S + kw]);
                    fma2(acc[px][0], ipk, wA.x);
                    fma2(acc[px][1], ipk, wA.y);
                    fma2(acc[px][2], ipk, wB.x);
                    fma2(acc[px][3], ipk, wB.y);
                }
            }
        }
    }

    const int oh = r0 + row;
#pragma unroll
    for (int cp = 0; cp < 4; cp++) {
        float lo[8], hi[8];
#pragma unroll
        for (int px = 0; px < 8; px++) {
            float2 t = unpk(acc[px][cp]);
            lo[px] = t.x; hi[px] = t.y;
        }
#pragma unroll
        for (int h = 0; h < 2; h++) {
            const float* src = h ? hi : lo;
            int co = co0 + cp * 2 + h;
            float bv = bias ? bias[co] : 0.f;
            size_t base = (((size_t)n * Cout + co) * Hout + oh) * Wout + c0 + col8;
            float4 v0 = make_float4(src[0] + bv, src[1] + bv, src[2] + bv, src[3] + bv);
            float4 v1 = make_float4(src[4] + bv, src[5] + bv, src[6] + bv, src[7] + bv);
            if (resid) {
                float4 ra = *(const float4*)(resid + base);
                float4 rb = *(const float4*)(resid + base + 4);
                v0.x += ra.x; v0.y += ra.y; v0.z += ra.z; v0.w += ra.w;
                v1.x += rb.x; v1.y += rb.y; v1.z += rb.z; v1.w += rb.w;
            }
            if (out_relu) {
                v0.x = fmaxf(v0.x, 0.f); v0.y = fmaxf(v0.y, 0.f);
                v0.z = fmaxf(v0.z, 0.f); v0.w = fmaxf(v0.w, 0.f);
                v1.x = fmaxf(v1.x, 0.f); v1.y = fmaxf(v1.y, 0.f);
                v1.z = fmaxf(v1.z, 0.f); v1.w = fmaxf(v1.w, 0.f);
            }
            *(float4*)(out + base) = v0;
            *(float4*)(out + base + 4) = v1;
        }
    }
}

// ---------------- 1x1 conv over 32x32 planes, 8co, f32x2 ----------------
__global__ void __launch_bounds__(256) conv1x1_8(
    const float* __restrict__ in, const float* __restrict__ w,
    const float* __restrict__ bias, const float* __restrict__ resid,
    float* __restrict__ out, int Cin, int Cout, int in_relu, int out_relu)
{
    __shared__ float wsm[128 * 8];
    const int tid = threadIdx.x;
    const int co0 = blockIdx.x * 8;
    const int n = blockIdx.y;
    for (int j = tid; j < Cin; j += 256) {
#pragma unroll
        for (int c = 0; c < 8; c++)
            wsm[j * 8 + c] = w[(size_t)(co0 + c) * Cin + j];
    }
    __syncthreads();

    const int px0 = tid * 4;
    const float* ip = in + (size_t)n * Cin * 1024 + px0;

    unsigned long long acc[4][4];
#pragma unroll
    for (int a = 0; a < 4; a++)
#pragma unroll
        for (int b = 0; b < 4; b++) acc[a][b] = 0ull;

    for (int ci = 0; ci < Cin; ci++) {
        float4 v = *(const float4*)(ip + (size_t)ci * 1024);
        if (in_relu) {
            v.x = fmaxf(v.x, 0.f); v.y = fmaxf(v.y, 0.f);
            v.z = fmaxf(v.z, 0.f); v.w = fmaxf(v.w, 0.f);
        }
        const ulonglong2* wp = (const ulonglong2*)(wsm + ci * 8);
        ulonglong2 wA = wp[0], wB = wp[1];
        float pxv[4] = {v.x, v.y, v.z, v.w};
#pragma unroll
        for (int px = 0; px < 4; px++) {
            unsigned long long ipk = splat2(pxv[px]);
            fma2(acc[px][0], ipk, wA.x);
            fma2(acc[px][1], ipk, wA.y);
            fma2(acc[px][2], ipk, wB.x);
            fma2(acc[px][3], ipk, wB.y);
        }
    }

#pragma unroll
    for (int cp = 0; cp < 4; cp++) {
        float lo[4], hi[4];
#pragma unroll
        for (int px = 0; px < 4; px++) {
            float2 t = unpk(acc[px][cp]);
            lo[px] = t.x; hi[px] = t.y;
        }
#pragma unroll
        for (int h = 0; h < 2; h++) {
            const float* src = h ? hi : lo;
            int co = co0 + cp * 2 + h;
            float bv = bias ? bias[co] : 0.f;
            size_t base = ((size_t)n * Cout + co) * 1024 + px0;
            float4 r = make_float4(src[0] + bv, src[1] + bv, src[2] + bv, src[3] + bv);
            if (resid) {
                float4 rs = *(const float4*)(resid + base);
                r.x += rs.x; r.y += rs.y; r.z += rs.z; r.w += rs.w;
            }
            if (out_relu) {
                r.x = fmaxf(r.x, 0.f); r.y = fmaxf(r.y, 0.f);
                r.z = fmaxf(r.z, 0.f); r.w = fmaxf(r.w, 0.f);
            }
            *(float4*)(out + base) = r;
        }
    }
}

// ---------------- ConvTranspose k=4 s=2 p=1, 8co x 8px, f32x2 (tc1) ----------------
template <int CIN>
__global__ void __launch_bounds__(128) convt8(
    const float* __restrict__ in, const float* __restrict__ w,
    const float* __restrict__ bias, float* __restrict__ out,
    int Cout, int Hin, int Win, int Hout, int Wout, int in_relu, int out_relu)
{
    extern __shared__ float smem[];
    float* wsm = smem;                  // CIN*16*8
    float* tile = smem + CIN * 128;     // 18 rows x 20 stride
    constexpr int TIP = 20;

    const int tid = threadIdx.x;
    const int co0 = blockIdx.x * 8;
    const int n = blockIdx.y;
    const int tilesX = Wout >> 5;
    const int ty = blockIdx.z / tilesX, tx = blockIdx.z % tilesX;
    const int r0 = ty * 32, c0 = tx * 32;
    const int base_i = (r0 >> 1) - 1, base_j = (c0 >> 1) - 1;

    for (int j = tid; j < CIN * 16; j += 128) {
#pragma unroll
        for (int c = 0; c < 8; c++)
            wsm[j * 8 + c] = w[((size_t)(j >> 4) * Cout + co0 + c) * 16 + (j & 15)];
    }

    const int row = tid >> 2;
    const int col8 = (tid & 3) << 3;
    const int oh = r0 + row;
    const int kh_a = (oh + 1) & 1;
    const int ta = ((oh + 1 - kh_a) >> 1) - base_i;
    const int tb = ta - 1;
    const int j0 = col8 >> 1;

    unsigned long long acc[8][4];
#pragma unroll
    for (int a = 0; a < 8; a++)
#pragma unroll
        for (int b = 0; b < 4; b++) acc[a][b] = 0ull;

    const float* inb = in + (size_t)n * CIN * Hin * Win;

    for (int ci = 0; ci < CIN; ci++) {
        __syncthreads();
        for (int i = tid; i < 324; i += 128) {
            int tr = i / 18, tc = i - tr * 18;
            int gi = base_i + tr, gj = base_j + tc;
            float v = 0.f;
            if (gi >= 0 && gi < Hin && gj >= 0 && gj < Win)
                v = inb[((size_t)ci * Hin + gi) * Win + gj];
            if (in_relu) v = fmaxf(v, 0.f);
            tile[tr * TIP + tc] = v;
        }
        __syncthreads();

        float rgA[8], rgB[8];
        *(float4*)&rgA[0] = *(const float4*)(tile + ta * TIP + j0);
        *(float4*)&rgA[4] = *(const float4*)(tile + ta * TIP + j0 + 4);
        *(float4*)&rgB[0] = *(const float4*)(tile + tb * TIP + j0);
        *(float4*)&rgB[4] = *(const float4*)(tile + tb * TIP + j0 + 4);

        const ulonglong2* wp = (const ulonglong2*)(wsm + ci * 128);
        ulonglong2 wa0[4], wa1[4], wb0[4], wb1[4];
#pragma unroll
        for (int kw = 0; kw < 4; kw++) {
            int tA = (kh_a * 4 + kw) * 2;
            int tB = ((kh_a + 2) * 4 + kw) * 2;
            wa0[kw] = wp[tA];     wa1[kw] = wp[tA + 1];
            wb0[kw] = wp[tB];     wb1[kw] = wp[tB + 1];
        }

#pragma unroll
        for (int px = 0; px < 8; px++) {
            constexpr_helper:;
            const int kw_a = ((px & 1) ^ 1);
            const int ja = ((px + 1 - kw_a) >> 1) + 1;
            const int jb = ja - 1;
            unsigned long long paa = splat2(rgA[ja]);
            unsigned long long pab = splat2(rgA[jb]);
            unsigned long long pba = splat2(rgB[ja]);
            unsigned long long pbb = splat2(rgB[jb]);
            fma2(acc[px][0], paa, wa0[kw_a].x);
            fma2(acc[px][1], paa, wa0[kw_a].y);
            fma2(acc[px][2], paa, wa1[kw_a].x);
            fma2(acc[px][3], paa, wa1[kw_a].y);
            fma2(acc[px][0], pab, wa0[kw_a + 2].x);
            fma2(acc[px][1], pab, wa0[kw_a + 2].y);
            fma2(acc[px][2], pab, wa1[kw_a + 2].x);
            fma2(acc[px][3], pab, wa1[kw_a + 2].y);
            fma2(acc[px][0], pba, wb0[kw_a].x);
            fma2(acc[px][1], pba, wb0[kw_a].y);
            fma2(acc[px][2], pba, wb1[kw_a].x);
            fma2(acc[px][3], pba, wb1[kw_a].y);
            fma2(acc[px][0], pbb, wb0[kw_a + 2].x);
            fma2(acc[px][1], pbb, wb0[kw_a + 2].y);
            fma2(acc[px][2], pbb, wb1[kw_a + 2].x);
            fma2(acc[px][3], pbb, wb1[kw_a + 2].y);
        }
    }

#pragma unroll
    for (int cp = 0; cp < 4; cp++) {
        float lo[8], hi[8];
#pragma unroll
        for (int px = 0; px < 8; px++) {
            float2 t = unpk(acc[px][cp]);
            lo[px] = t.x; hi[px] = t.y;
        }
#pragma unroll
        for (int h = 0; h < 2; h++) {
            const float* src = h ? hi : lo;
            int co = co0 + cp * 2 + h;
            float bv = bias ? bias[co] : 0.f;
            size_t base = (((size_t)n * Cout + co) * Hout + oh) * Wout + c0 + col8;
            float4 v0 = make_float4(src[0] + bv, src[1] + bv, src[2] + bv, src[3] + bv);
            float4 v1 = make_float4(src[4] + bv, src[5] + bv, src[6] + bv, src[7] + bv);
            if (out_relu) {
                v0.x = fmaxf(v0.x, 0.f); v0.y = fmaxf(v0.y, 0.f);
                v0.z = fmaxf(v0.z, 0.f); v0.w = fmaxf(v0.w, 0.f);
                v1.x = fmaxf(v1.x, 0.f); v1.y = fmaxf(v1.y, 0.f);
                v1.z = fmaxf(v1.z, 0.f); v1.w = fmaxf(v1.w, 0.f);
            }
            *(float4*)(out + base) = v0;
            *(float4*)(out + base + 4) = v1;
        }
    }
}

// ---------------- ConvTranspose scalar (for tiny tc2, Cout=3) ----------------
template <int CIN>
__global__ void __launch_bounds__(256) convt421(
    const float* __restrict__ in, const float* __restrict__ w,
    const float* __restrict__ bias, float* __restrict__ out,
    int Cout, int Hin, int Win, int Hout, int Wout, int in_relu, int out_relu)
{
    __shared__ float tile[18 * 18];
    __shared__ float4 wsm[CIN * 16];

    const int tid = threadIdx.x;
    const int co0 = blockIdx.x * 4;
    const int n = blockIdx.y;
    const int tilesX = Wout >> 5;
    const int ty = blockIdx.z / tilesX, tx = blockIdx.z % tilesX;
    const int r0 = ty * 32, c0 = tx * 32;
    const int base_i = (r0 >> 1) - 1, base_j = (c0 >> 1) - 1;

    float* wsm_f = (float*)wsm;
#pragma unroll
    for (int c = 0; c < 4; c++) {
        int co = co0 + c;
        for (int j = tid; j < CIN * 16; j += 256)
            wsm_f[j * 4 + c] =
                (co < Cout) ? w[((size_t)(j >> 4) * Cout + co) * 16 + (j & 15)] : 0.f;
    }

    const int row = tid >> 3;
    const int col4 = (tid & 7) << 2;
    const int oh = r0 + row;
    const int kh_a = (oh + 1) & 1;
    const int ih_a = (oh + 1 - kh_a) >> 1;
    const int ta = ih_a - base_i;
    const int tb = ta - 1;

    float acc[4][4];
#pragma unroll
    for (int a = 0; a < 4; a++)
#pragma unroll
        for (int b = 0; b < 4; b++) acc[a][b] = 0.f;

    const float* inb = in + (size_t)n * CIN * Hin * Win;

    for (int ci = 0; ci < CIN; ci++) {
        __syncthreads();
        for (int i = tid; i < 324; i += 256) {
            int tr = i / 18, tc = i % 18;
            int gi = base_i + tr, gj = base_j + tc;
            float v = 0.f;
            if (gi >= 0 && gi < Hin && gj >= 0 && gj < Win)
                v = inb[((size_t)ci * Hin + gi) * Win + gj];
            if (in_relu) v = fmaxf(v, 0.f);
            tile[i] = v;
        }
        __syncthreads();

        const float4* wp = wsm + ci * 16;
#pragma unroll
        for (int px = 0; px < 4; px++) {
            int ow = c0 + col4 + px;
            int kw_a = (ow + 1) & 1;
            int ja = ((ow + 1 - kw_a) >> 1) - base_j;
            int jb = ja - 1;
            float iaa = tile[ta * 18 + ja], iab = tile[ta * 18 + jb];
            float iba = tile[tb * 18 + ja], ibb = tile[tb * 18 + jb];
            float4 waa = wp[kh_a * 4 + kw_a];
            float4 wab = wp[kh_a * 4 + kw_a + 2];
            float4 wba = wp[(kh_a + 2) * 4 + kw_a];
            float4 wbb = wp[(kh_a + 2) * 4 + kw_a + 2];
            acc[px][0] = fmaf(iaa, waa.x, fmaf(iab, wab.x, fmaf(iba, wba.x, fmaf(ibb, wbb.x, acc[px][0]))));
            acc[px][1] = fmaf(iaa, waa.y, fmaf(iab, wab.y, fmaf(iba, wba.y, fmaf(ibb, wbb.y, acc[px][1]))));
            acc[px][2] = fmaf(iaa, waa.z, fmaf(iab, wab.z, fmaf(iba, wba.z, fmaf(ibb, wbb.z, acc[px][2]))));
            acc[px][3] = fmaf(iaa, waa.w, fmaf(iab, wab.w, fmaf(iba, wba.w, fmaf(ibb, wbb.w, acc[px][3]))));
        }
    }

#pragma unroll
    for (int c = 0; c < 4; c++) {
        int co = co0 + c;
        if (co >= Cout) continue;
        float bv = bias ? bias[co] : 0.f;
        size_t base = (((size_t)n * Cout + co) * Hout + oh) * Wout + c0 + col4;
#pragma unroll
        for (int px = 0; px < 4; px++) {
            float v = acc[px][c] + bv;
            if (out_relu) v = fmaxf(v, 0.f);
            out[base + px] = v;
        }
    }
}

// ---------------- VQ (f32x2 dot) ----------------
__global__ void __launch_bounds__(512) vq_kernel(
    const float* __restrict__ Ze, const float* __restrict__ E,
    float* __restrict__ Zq, float* __restrict__ counts, float* __restrict__ loss_sum)
{
    extern __shared__ float Es[];          // 512*64 floats = 128 KB
    __shared__ float e2s[512];
    __shared__ float red[512];
    const int tid = threadIdx.x;

    for (int i = tid * 4; i < 512 * 64; i += 512 * 4)
        *(float4*)&Es[i] = *(const float4*)&E[i];
    __syncthreads();

    {
        const float* er = &Es[tid * 64];
        float s = 0.f;
#pragma unroll
        for (int d = 0; d < 64; d++) s = fmaf(er[d], er[d], s);
        e2s[tid] = s;
    }
    __syncthreads();

    const int vi = blockIdx.x * 512 + tid;
    const int b = vi >> 10;
    const int hw = vi & 1023;
    const float* zp = Ze + (size_t)b * 64 * 1024 + hw;

    unsigned long long vp[32];
    float sv = 0.f;
#pragma unroll
    for (int j = 0; j < 32; j++) {
        float a = zp[(size_t)(2 * j) * 1024];
        float c = zp[(size_t)(2 * j + 1) * 1024];
        sv = fmaf(a, a, fmaf(c, c, sv));
        vp[j] = pack2(a, c);
    }

    float best = 3.402823466e38f;
    int bi = 0;
    for (int k = 0; k < 512; k++) {
        const ulonglong2* er = (const ulonglong2*)&Es[k * 64];
        unsigned long long dp = 0ull;
#pragma unroll
        for (int j = 0; j < 16; j++) {
            ulonglong2 e = er[j];
            fma2(dp, vp[2 * j], e.x);
            fma2(dp, vp[2 * j + 1], e.y);
        }
        float2 dd = unpk(dp);
        float dist = sv + e2s[k] - 2.f * (dd.x + dd.y);
        if (dist < best) { best = dist; bi = k; }
    }

    float le = 0.f;
    float* qp = Zq + (size_t)b * 64 * 1024 + hw;
    const float* eb = &Es[bi * 64];
#pragma unroll
    for (int j = 0; j < 32; j++) {
        float2 v2 = unpk(vp[j]);
        float q0 = eb[2 * j], q1 = eb[2 * j + 1];
        qp[(size_t)(2 * j) * 1024] = q0;
        qp[(size_t)(2 * j + 1) * 1024] = q1;
        float d0 = q0 - v2.x, d1 = q1 - v2.y;
        le = fmaf(d0, d0, fmaf(d1, d1, le));
    }
    atomicAdd(&counts[bi], 1.0f);

    red[tid] = le;
    __syncthreads();
    for (int s = 256; s > 0; s >>= 1) {
        if (tid < s) red[tid] += red[tid + s];
        __syncthreads();
    }
    if (tid == 0) atomicAdd(loss_sum, red[0]);
}

__global__ void zero_small(float* counts, float* loss) {
    int t = blockIdx.x * blockDim.x + threadIdx.x;
    if (t < 512) counts[t] = 0.f;
    if (t == 0) loss[0] = 0.f;
}

__global__ void finalize_kernel(const float* __restrict__ counts,
                                const float* __restrict__ loss_sum,
                                float* __restrict__ out, int out_size) {
    __shared__ float red[512];
    int tid = threadIdx.x;
    float c = counts[tid];
    float p = c * (1.0f / 65536.0f);
    red[tid] = p * log2f(p + 1e-10f);
    __syncthreads();
    for (int s = 256; s > 0; s >>= 1) {
        if (tid < s) red[tid] += red[tid + s];
        __syncthreads();
    }
    if (tid == 0) {
        float ent = -red[0];
        float mse = loss_sum[0] * (1.0f / 4194304.0f);
        out[0] = mse + 0.25f * mse;
        out[out_size - 3] = mse;
        out[out_size - 2] = mse;
        out[out_size - 1] = exp2f(ent);
    }
}

// ---------------- host launcher ----------------
extern "C" void kernel_launch(void* const* d_in, const int* in_sizes, int n_in,
                              void* d_out, int out_size) {
    const float* x         = (const float*)d_in[0];
    const float* enc_w1    = (const float*)d_in[1];
    const float* enc_b1    = (const float*)d_in[2];
    const float* enc_w2    = (const float*)d_in[3];
    const float* enc_b2    = (const float*)d_in[4];
    const float* enc_w3    = (const float*)d_in[5];
    const float* enc_b3    = (const float*)d_in[6];
    const float* enc_w4    = (const float*)d_in[7];
    const float* enc_b4    = (const float*)d_in[8];
    const float* enc_res_w1= (const float*)d_in[9];
    const float* enc_res_w2= (const float*)d_in[10];
    const float* enc_adj_w = (const float*)d_in[11];
    const float* enc_adj_b = (const float*)d_in[12];
    const float* E         = (const float*)d_in[13];
    const float* dec_adj_w = (const float*)d_in[14];
    const float* dec_adj_b = (const float*)d_in[15];
    const float* dec_res_w1= (const float*)d_in[16];
    const float* dec_res_w2= (const float*)d_in[17];
    const float* tc1_w     = (const float*)d_in[18];
    const float* tc1_b     = (const float*)d_in[19];
    const float* tc2_w     = (const float*)d_in[20];
    const float* tc2_b     = (const float*)d_in[21];
    float* out = (float*)d_out;

    float *b1, *b2, *b3, *b4, *b5, *cnt, *lsum;
    cudaGetSymbolAddress((void**)&b1, g_buf1);
    cudaGetSymbolAddress((void**)&b2, g_buf2);
    cudaGetSymbolAddress((void**)&b3, g_buf3);
    cudaGetSymbolAddress((void**)&b4, g_buf4);
    cudaGetSymbolAddress((void**)&b5, g_buf5);
    cudaGetSymbolAddress((void**)&cnt, g_counts);
    cudaGetSymbolAddress((void**)&lsum, g_loss);

    // dynamic smem sizes
    const int sm_e1 = (3 * 16 * 8 + 66 * 68) * 4;      // 19488
    const int sm_e2 = (64 * 16 * 8 + 66 * 68) * 4;     // 50720
    const int sm_33 = (128 * 9 * 8 + 34 * 36) * 4;     // 41760
    const int sm_36 = (64 * 9 * 8 + 34 * 36) * 4;      // 23328
    const int sm_t8 = (128 * 128 + 18 * 20) * 4;       // 66976

    cudaFuncSetAttribute(conv_tiled8<4, 2, 64>, cudaFuncAttributeMaxDynamicSharedMemorySize, sm_e2);
    cudaFuncSetAttribute(convt8<128>, cudaFuncAttributeMaxDynamicSharedMemorySize, sm_t8);
    cudaFuncSetAttribute(vq_kernel, cudaFuncAttributeMaxDynamicSharedMemorySize, 131072);

    const int B = 64;

    // -------- encoder --------
    conv_tiled8<4, 2, 3><<<dim3(8, B, 4), 128, sm_e1>>>(x, enc_w1, enc_b1, nullptr, b1,
                                                        64, 128, 128, 64, 64, 0, 1);
    conv_tiled8<4, 2, 64><<<dim3(16, B, 1), 128, sm_e2>>>(b1, enc_w2, enc_b2, nullptr, b2,
                                                          128, 64, 64, 32, 32, 0, 1);
    conv_tiled8<3, 1, 128><<<dim3(16, B, 1), 128, sm_33>>>(b2, enc_w3, enc_b3, nullptr, b3,
                                                           128, 32, 32, 32, 32, 0, 1);
    conv_tiled8<3, 1, 128><<<dim3(16, B, 1), 128, sm_33>>>(b3, enc_w4, enc_b4, nullptr, b2,
                                                           128, 32, 32, 32, 32, 0, 0);
    // res block 1
    conv_tiled8<3, 1, 128><<<dim3(8, B, 1), 128, sm_33>>>(b2, enc_res_w1, nullptr, nullptr, b4,
                                                          64, 32, 32, 32, 32, 1, 0);
    conv1x1_8<<<dim3(16, B), 256>>>(b4, enc_res_w2, nullptr, b2, b3, 64, 128, 1, 0);
    // res block 2
    conv_tiled8<3, 1, 128><<<dim3(8, B, 1), 128, sm_33>>>(b3, enc_res_w1 + 64 * 128 * 9, nullptr,
                                                          nullptr, b4, 64, 32, 32, 32, 32, 1, 0);
    conv1x1_8<<<dim3(16, B), 256>>>(b4, enc_res_w2 + 128 * 64, nullptr, b3, b2, 64, 128, 1, 0);
    // enc_adj
    conv1x1_8<<<dim3(8, B), 256>>>(b2, enc_adj_w, enc_adj_b, nullptr, b5, 128, 64, 1, 0);

    // -------- vector quantizer --------
    zero_small<<<2, 256>>>(cnt, lsum);
    vq_kernel<<<128, 512, 131072>>>(b5, E, b4, cnt, lsum);

    // -------- decoder --------
    conv_tiled8<3, 1, 64><<<dim3(16, B, 1), 128, sm_36>>>(b4, dec_adj_w, dec_adj_b, nullptr, b2,
                                                          128, 32, 32, 32, 32, 0, 0);
    conv_tiled8<3, 1, 128><<<dim3(8, B, 1), 128, sm_33>>>(b2, dec_res_w1, nullptr, nullptr, b4,
                                                          64, 32, 32, 32, 32, 1, 0);
    conv1x1_8<<<dim3(16, B), 256>>>(b4, dec_res_w2, nullptr, b2, b3, 64, 128, 1, 0);
    conv_tiled8<3, 1, 128><<<dim3(8, B, 1), 128, sm_33>>>(b3, dec_res_w1 + 64 * 128 * 9, nullptr,
                                                          nullptr, b4, 64, 32, 32, 32, 32, 1, 0);
    conv1x1_8<<<dim3(16, B), 256>>>(b4, dec_res_w2 + 128 * 64, nullptr, b3, b2, 64, 128, 1, 0);

    convt8<128><<<dim3(8, B, 4), 128, sm_t8>>>(b2, tc1_w, tc1_b, b1,
                                               64, 32, 32, 64, 64, 1, 1);
    convt421<64><<<dim3(1, B, 16), 256>>>(b1, tc2_w, tc2_b, out + 1,
                                          3, 64, 64, 128, 128, 0, 0);

    finalize_kernel<<<1, 512>>>(cnt, lsum, out, out_size);
}

// round 5
// speedup vs baseline: 2.5848x; 2.5848x over previous
#include <cuda_runtime.h>
#include <cuda_bf16.h>
#include <math.h>
#include <stdint.h>

// ---- arch gate: tcgen05 only exists on arch-specific (sm_103a/sm_100a) passes ----
#if defined(__CUDA_ARCH_FEAT_SM103_ALL) || defined(__CUDA_ARCH_FEAT_SM100_ALL) || \
    defined(__CUDA_ARCH_FEAT_SM101_ALL) || defined(__CUDA_ARCH_SPECIFIC__)
#define HAS_TC5 1
#else
#define HAS_TC5 0
#endif

// ================= PTX helpers =================
__device__ __forceinline__ uint32_t smem_u32(const void* p) {
    uint32_t a;
    asm("{ .reg .u64 t; cvta.to.shared.u64 t, %1; cvt.u32.u64 %0, t; }" : "=r"(a) : "l"(p));
    return a;
}
__device__ __forceinline__ uint32_t elect1() {
    uint32_t r;
    asm volatile("{ .reg .pred p; elect.sync _|p, 0xFFFFFFFF; selp.b32 %0, 1, 0, p; }" : "=r"(r));
    return r;
}
__device__ __forceinline__ float tf32r(float x) {
    uint32_t u;
    asm("cvt.rna.tf32.f32 %0, %1;" : "=r"(u) : "f"(x));
    return __uint_as_float(u);
}
__device__ __forceinline__ uint64_t mkdesc(uint32_t addr) {
    const uint64_t BASE = (uint64_t(2) << 61) | (uint64_t(1) << 46) |
                          (uint64_t(64) << 32) | (uint64_t(1) << 16);
    return BASE | ((addr >> 4) & 0x3FFF);
}
#define SWZ(x) ((x) ^ (((x) >> 3) & 0x70))
#define MBAR_INIT(a, n) \
    asm volatile("mbarrier.init.shared.b64 [%0], %1;" :: "r"(a), "r"(n) : "memory")
#define MBAR_WAIT(a, ph) do {                                                      \
    uint32_t _m = (a), _p = (ph), _d;                                              \
    asm volatile("{ .reg .pred p; mbarrier.try_wait.parity.acquire.cta.shared::cta.b64 p, [%1], %2; selp.b32 %0,1,0,p; }" \
                 : "=r"(_d) : "r"(_m), "r"(_p) : "memory");                        \
    if (!_d) {                                                                     \
        asm volatile("{ .reg .pred P1;\n"                                          \
            "W%=: mbarrier.try_wait.parity.acquire.cta.shared::cta.b64 P1, [%0], %1, 0x989680;\n" \
            "@P1 bra.uni D%=;\n bra.uni W%=;\n D%=: }"                             \
            :: "r"(_m), "r"(_p) : "memory");                                       \
    } } while (0)

#if HAS_TC5
#define TC_ALLOC(sa, n)  asm volatile("tcgen05.alloc.cta_group::1.sync.aligned.shared::cta.b32 [%0], %1;" :: "r"(sa), "r"(n) : "memory")
#define TC_DEALLOC(t, n) asm volatile("tcgen05.dealloc.cta_group::1.sync.aligned.b32 %0, %1;" :: "r"(t), "r"(n))
#define TC_RELINQ()      asm volatile("tcgen05.relinquish_alloc_permit.cta_group::1.sync.aligned;")
#define TC_COMMIT(mb)    asm volatile("tcgen05.commit.cta_group::1.mbarrier::arrive::one.shared::cluster.b64 [%0];" :: "r"(mb) : "memory")
#define TC_FENCE_AFTER() asm volatile("tcgen05.fence::after_thread_sync;" ::: "memory")
#define TC_WAIT_LD()     asm volatile("tcgen05.wait::ld.sync.aligned;" ::: "memory")
#define FENCE_ASYNC()    asm volatile("fence.proxy.async.shared::cta;" ::: "memory")

__device__ __forceinline__ void mma_tf32(uint32_t d, uint64_t ad, uint64_t bd,
                                         uint32_t idesc, uint32_t en) {
    asm volatile(
        "{ .reg .pred p; setp.ne.u32 p, %4, 0;\n\t"
        "tcgen05.mma.cta_group::1.kind::tf32 [%0], %1, %2, %3, {%5, %5, %5, %5}, p;\n\t}"
        :: "r"(d), "l"(ad), "l"(bd), "r"(idesc), "r"(en), "r"(0u) : "memory");
}
#define LDTM32(r, ta) \
    asm volatile( \
        "tcgen05.ld.sync.aligned.32x32b.x32.b32 " \
        "{%0,%1,%2,%3,%4,%5,%6,%7,%8,%9,%10,%11,%12,%13,%14,%15," \
        "%16,%17,%18,%19,%20,%21,%22,%23,%24,%25,%26,%27,%28,%29,%30,%31}, [%32];" \
        : "=r"((r)[0]), "=r"((r)[1]), "=r"((r)[2]), "=r"((r)[3]), \
          "=r"((r)[4]), "=r"((r)[5]), "=r"((r)[6]), "=r"((r)[7]), \
          "=r"((r)[8]), "=r"((r)[9]), "=r"((r)[10]), "=r"((r)[11]), \
          "=r"((r)[12]), "=r"((r)[13]), "=r"((r)[14]), "=r"((r)[15]), \
          "=r"((r)[16]), "=r"((r)[17]), "=r"((r)[18]), "=r"((r)[19]), \
          "=r"((r)[20]), "=r"((r)[21]), "=r"((r)[22]), "=r"((r)[23]), \
          "=r"((r)[24]), "=r"((r)[25]), "=r"((r)[26]), "=r"((r)[27]), \
          "=r"((r)[28]), "=r"((r)[29]), "=r"((r)[30]), "=r"((r)[31]) \
        : "r"(ta))
#endif  // HAS_TC5

// ================= scratch =================
__device__ float g_buf1[64 * 64 * 64 * 64];
__device__ float g_buf2[64 * 128 * 32 * 32];
__device__ float g_buf3[64 * 128 * 32 * 32];
__device__ float g_buf4[64 * 64 * 32 * 32];
__device__ float g_buf5[64 * 64 * 32 * 32];
__device__ float g_wt[794624];
__device__ float g_counts[512];
__device__ float g_loss[1];

// ================= weight transform (co,ci,t) -> [co][t][ci] =================
__global__ void wtrans(const float* __restrict__ src, float* __restrict__ dst,
                       int CO, int CI, int T) {
    int i = blockIdx.x * 256 + threadIdx.x;
    if (i < CO * CI * T) {
        int t = i % T;
        int ci = (i / T) % CI;
        int co = i / (T * CI);
        dst[co * CI * T + t * CI + ci] = src[i];
    }
}

// ================= conv for 32x32 outputs: tcgen05 tf32, scalar fallback =================
// block: (image n, 128-pixel M-tile mt). Bt layout: [co][tap][ci].
template <int CIN, int KSZ, int S, int NCO, int HIN>
__global__ void __launch_bounds__(256) conv_tc(
    const float* __restrict__ in, const float* __restrict__ Bt,
    const float* __restrict__ bias, const float* __restrict__ resid,
    float* __restrict__ out, int in_relu, int out_relu)
{
    constexpr int T = KSZ * KSZ;
    constexpr int P = (KSZ == 1) ? 0 : 1;
    const int tid = threadIdx.x;
    const int mt = blockIdx.x;
    const int n = blockIdx.y;
    const float* inb = in + (size_t)n * CIN * (HIN * HIN);

#if HAS_TC5
    constexpr int GCI = CIN / 32;
    constexpr int NCH = T * GCI;
    constexpr int BB = NCO * 128;
    constexpr uint32_t IDESC =
        (1u << 4) | (2u << 7) | (2u << 10) | ((uint32_t)(NCO / 8) << 17) | (8u << 24);

    extern __shared__ char smem[];
    const uint32_t sb = smem_u32(smem);
    const uint32_t mb0 = sb + 16, mb1 = sb + 24;
    char* Ab = smem + 1024;
    char* Bb = smem + 1024 + 32768;

    const int wid = tid >> 5, lid = tid & 31;

    if (tid == 0) { MBAR_INIT(mb0, 1); MBAR_INIT(mb1, 1); }
    if (wid == 0) { TC_ALLOC(sb, 128); TC_RELINQ(); }
    __syncthreads();
    uint32_t tmem;
    asm volatile("ld.shared.b32 %0, [%1];" : "=r"(tmem) : "r"(sb));

    int ph0 = 0, ph1 = 0;
    for (int c = 0; c < NCH; c++) {
        const int bsel = c & 1;
        if (c >= 2) {
            if (bsel == 0) { MBAR_WAIT(mb0, ph0); ph0 ^= 1; }
            else           { MBAR_WAIT(mb1, ph1); ph1 ^= 1; }
        }
        const int t = c / GCI;
        const int g = c - t * GCI;
        const int kh = t / KSZ, kw = t - kh * KSZ;
        char* A = Ab + bsel * 16384;
        char* B = Bb + bsel * BB;

#pragma unroll
        for (int it = 0; it < 4; it++) {
            int slot = tid + it * 256;
            int jg = slot >> 7;
            int m = slot & 127;
            int oh = (mt << 2) + (m >> 5);
            int ow = m & 31;
            int ih = oh * S - P + kh;
            int iw = ow * S - P + kw;
            float4 v = make_float4(0.f, 0.f, 0.f, 0.f);
            if (ih >= 0 && ih < HIN && iw >= 0 && iw < HIN) {
                const float* p = inb + (size_t)(g * 32 + jg * 4) * (HIN * HIN) + ih * HIN + iw;
                v.x = p[0];
                v.y = p[HIN * HIN];
                v.z = p[2 * HIN * HIN];
                v.w = p[3 * HIN * HIN];
            }
            if (in_relu) {
                v.x = fmaxf(v.x, 0.f); v.y = fmaxf(v.y, 0.f);
                v.z = fmaxf(v.z, 0.f); v.w = fmaxf(v.w, 0.f);
            }
            v.x = tf32r(v.x); v.y = tf32r(v.y); v.z = tf32r(v.z); v.w = tf32r(v.w);
            *(float4*)(A + SWZ(m * 128 + jg * 16)) = v;
        }
#pragma unroll
        for (int it = 0; it < NCO / 32; it++) {
            int slot = tid + it * 256;
            int jg = slot & 7;
            int co = slot >> 3;
            float4 v = *(const float4*)(Bt + (size_t)co * (T * CIN) + t * CIN + g * 32 + jg * 4);
            v.x = tf32r(v.x); v.y = tf32r(v.y); v.z = tf32r(v.z); v.w = tf32r(v.w);
            *(float4*)(B + SWZ(co * 128 + jg * 16)) = v;
        }
        FENCE_ASYNC();
        __syncthreads();
        if (wid == 0 && elect1()) {
            uint32_t aAddr = sb + 1024 + bsel * 16384;
            uint32_t bAddr = sb + 1024 + 32768 + bsel * BB;
            uint64_t ad = mkdesc(aAddr), bd = mkdesc(bAddr);
#pragma unroll
            for (int s2 = 0; s2 < 4; s2++)
                mma_tf32(tmem, ad + s2 * 2, bd + s2 * 2, IDESC, (c > 0 || s2 > 0) ? 1u : 0u);
            TC_COMMIT(bsel ? mb1 : mb0);
        }
        __syncthreads();
    }

    MBAR_WAIT(mb0, ph0);
    MBAR_WAIT(mb1, ph1);
    TC_FENCE_AFTER();

    if (wid < 4) {
        const int p = (mt << 7) + (wid << 5) + lid;
#pragma unroll
        for (int cb = 0; cb < NCO / 32; cb++) {
            uint32_t d[32];
            LDTM32(d, tmem + cb * 32);
            TC_WAIT_LD();
#pragma unroll
            for (int q = 0; q < 32; q++) {
                int co = cb * 32 + q;
                float v = __uint_as_float(d[q]);
                if (bias) v += bias[co];
                size_t o = (((size_t)n * NCO + co) << 10) + p;
                if (resid) v += resid[o];
                if (out_relu) v = fmaxf(v, 0.f);
                out[o] = v;
            }
        }
    }
    __syncthreads();
    if (wid == 0) TC_DEALLOC(tmem, 128);

#else  // ---------- scalar fallback (non-'a' compile pass) ----------
    constexpr int TIH = 3 * S + KSZ;
    constexpr int TIW = 31 * S + KSZ;
    extern __shared__ float fsm[];
    float* tile = fsm;               // TIH*TIW
    float* wci = fsm + TIH * TIW;    // T*NCO

    const int m = tid & 127;
    const int half = tid >> 7;
    const int ohl = m >> 5, ow = m & 31;
    const int rbase = (mt << 2) * S - P;

    float acc[NCO / 2];
#pragma unroll
    for (int j = 0; j < NCO / 2; j++) acc[j] = 0.f;

    for (int ci = 0; ci < CIN; ci++) {
        __syncthreads();
        const float* ip = inb + (size_t)ci * (HIN * HIN);
        for (int i = tid; i < TIH * TIW; i += 256) {
            int tr = i / TIW, tc = i - tr * TIW;
            int gr = rbase + tr, gc = tc - P;
            float v = 0.f;
            if (gr >= 0 && gr < HIN && gc >= 0 && gc < HIN) v = ip[gr * HIN + gc];
            if (in_relu) v = fmaxf(v, 0.f);
            tile[i] = v;
        }
        for (int i = tid; i < T * NCO; i += 256) {
            int t = i / NCO, co = i - t * NCO;
            wci[i] = Bt[(size_t)co * (T * CIN) + t * CIN + ci];
        }
        __syncthreads();
#pragma unroll
        for (int t = 0; t < T; t++) {
            int kh = t / KSZ, kw = t - kh * KSZ;
            float iv = tile[(ohl * S + kh) * TIW + ow * S + kw];
            const float4* wp = (const float4*)(wci + t * NCO + half * (NCO / 2));
#pragma unroll
            for (int j = 0; j < NCO / 8; j++) {
                float4 wv = wp[j];
                acc[4 * j + 0] = fmaf(iv, wv.x, acc[4 * j + 0]);
                acc[4 * j + 1] = fmaf(iv, wv.y, acc[4 * j + 1]);
                acc[4 * j + 2] = fmaf(iv, wv.z, acc[4 * j + 2]);
                acc[4 * j + 3] = fmaf(iv, wv.w, acc[4 * j + 3]);
            }
        }
    }

    const int p = (mt << 7) + m;
#pragma unroll
    for (int j = 0; j < NCO / 2; j++) {
        int co = half * (NCO / 2) + j;
        float v = acc[j];
        if (bias) v += bias[co];
        size_t o = (((size_t)n * NCO + co) << 10) + p;
        if (resid) v += resid[o];
        if (out_relu) v = fmaxf(v, 0.f);
        out[o] = v;
    }
#endif
}

// ================= scalar conv (conv1: 4x4 s2 CIN=3) =================
template <int K, int S, int CIN>
__global__ void __launch_bounds__(256) conv_tiled(
    const float* __restrict__ in, const float* __restrict__ w,
    const float* __restrict__ bias, float* __restrict__ out,
    int Cout, int Hin, int Win, int Hout, int Wout, int out_relu)
{
    constexpr int P = 1;
    constexpr int TI = 31 * S + K;
    constexpr int TILE_N = TI * TI;
    constexpr int NS = (TILE_N + 255) / 256;
    constexpr int RW = 3 * S + K;

    __shared__ float tile[TILE_N];
    __shared__ float4 wsm[CIN * K * K];

    const int tid = threadIdx.x;
    const int co0 = blockIdx.x * 4;
    const int n = blockIdx.y;
    const int tilesX = Wout >> 5;
    const int ty = blockIdx.z / tilesX, tx = blockIdx.z % tilesX;
    const int r0 = ty * 32, c0 = tx * 32;

    float* wsm_f = (float*)wsm;
#pragma unroll
    for (int c = 0; c < 4; c++) {
        const float* wp = w + (size_t)(co0 + c) * CIN * K * K;
        for (int j = tid; j < CIN * K * K; j += 256)
            wsm_f[j * 4 + c] = wp[j];
    }

    int goff[NS];
#pragma unroll
    for (int s = 0; s < NS; s++) {
        int i = tid + s * 256;
        goff[s] = -1;
        if (i < TILE_N) {
            int tr = i / TI, tc = i % TI;
            int gr = r0 * S - P + tr, gc = c0 * S - P + tc;
            if (gr >= 0 && gr < Hin && gc >= 0 && gc < Win) goff[s] = gr * Win + gc;
        }
    }

    const int row = tid >> 3;
    const int col4 = (tid & 7) << 2;

    float acc[4][4];
#pragma unroll
    for (int a = 0; a < 4; a++)
#pragma unroll
        for (int b = 0; b < 4; b++) acc[a][b] = 0.f;

    const float* inb = in + (size_t)n * CIN * Hin * Win;

    for (int ci = 0; ci < CIN; ci++) {
        __syncthreads();
        const float* ip = inb + (size_t)ci * Hin * Win;
#pragma unroll
        for (int s = 0; s < NS; s++) {
            int i = tid + s * 256;
            if (i < TILE_N) tile[i] = (goff[s] >= 0) ? ip[goff[s]] : 0.f;
        }
        __syncthreads();

        float rg[K][RW];
#pragma unroll
        for (int a = 0; a < K; a++)
#pragma unroll
            for (int b = 0; b < RW; b++)
                rg[a][b] = tile[(row * S + a) * TI + col4 * S + b];

        const float4* wp = wsm + ci * K * K;
#pragma unroll
        for (int kh = 0; kh < K; kh++)
#pragma unroll
            for (int kw = 0; kw < K; kw++) {
                float4 wv = wp[kh * K + kw];
#pragma unroll
                for (int px = 0; px < 4; px++) {
                    float iv = rg[kh][px * S + kw];
                    acc[px][0] = fmaf(iv, wv.x, acc[px][0]);
                    acc[px][1] = fmaf(iv, wv.y, acc[px][1]);
                    acc[px][2] = fmaf(iv, wv.z, acc[px][2]);
                    acc[px][3] = fmaf(iv, wv.w, acc[px][3]);
                }
            }
    }

#pragma unroll
    for (int c = 0; c < 4; c++) {
        int co = co0 + c;
        float bv = bias ? bias[co] : 0.f;
        size_t base = (((size_t)n * Cout + co) * Hout + r0 + row) * Wout + c0 + col4;
#pragma unroll
        for (int px = 0; px < 4; px++) {
            float v = acc[px][c] + bv;
            if (out_relu) v = fmaxf(v, 0.f);
            out[base + px] = v;
        }
    }
}

// ================= ConvTranspose k=4 s=2 p=1, scalar 4co =================
template <int CIN>
__global__ void __launch_bounds__(256) convt421(
    const float* __restrict__ in, const float* __restrict__ w,
    const float* __restrict__ bias, float* __restrict__ out,
    int Cout, int Hin, int Win, int Hout, int Wout, int in_relu, int out_relu)
{
    __shared__ float tile[18 * 18];
    __shared__ float4 wsm[CIN * 16];

    const int tid = threadIdx.x;
    const int co0 = blockIdx.x * 4;
    const int n = blockIdx.y;
    const int tilesX = Wout >> 5;
    const int ty = blockIdx.z / tilesX, tx = blockIdx.z % tilesX;
    const int r0 = ty * 32, c0 = tx * 32;
    const int base_i = (r0 >> 1) - 1, base_j = (c0 >> 1) - 1;

    float* wsm_f = (float*)wsm;
#pragma unroll
    for (int c = 0; c < 4; c++) {
        int co = co0 + c;
        for (int j = tid; j < CIN * 16; j += 256)
            wsm_f[j * 4 + c] =
                (co < Cout) ? w[((size_t)(j >> 4) * Cout + co) * 16 + (j & 15)] : 0.f;
    }

    const int row = tid >> 3;
    const int col4 = (tid & 7) << 2;
    const int oh = r0 + row;
    const int kh_a = (oh + 1) & 1;
    const int ta = ((oh + 1 - kh_a) >> 1) - base_i;
    const int tb = ta - 1;

    float acc[4][4];
#pragma unroll
    for (int a = 0; a < 4; a++)
#pragma unroll
        for (int b = 0; b < 4; b++) acc[a][b] = 0.f;

    const float* inb = in + (size_t)n * CIN * Hin * Win;

    for (int ci = 0; ci < CIN; ci++) {
        __syncthreads();
        for (int i = tid; i < 324; i += 256) {
            int tr = i / 18, tc = i % 18;
            int gi = base_i + tr, gj = base_j + tc;
            float v = 0.f;
            if (gi >= 0 && gi < Hin && gj >= 0 && gj < Win)
                v = inb[((size_t)ci * Hin + gi) * Win + gj];
            if (in_relu) v = fmaxf(v, 0.f);
            tile[i] = v;
        }
        __syncthreads();

        const float4* wp = wsm + ci * 16;
#pragma unroll
        for (int px = 0; px < 4; px++) {
            int ow = c0 + col4 + px;
            int kw_a = (ow + 1) & 1;
            int ja = ((ow + 1 - kw_a) >> 1) - base_j;
            int jb = ja - 1;
            float iaa = tile[ta * 18 + ja], iab = tile[ta * 18 + jb];
            float iba = tile[tb * 18 + ja], ibb = tile[tb * 18 + jb];
            float4 waa = wp[kh_a * 4 + kw_a];
            float4 wab = wp[kh_a * 4 + kw_a + 2];
            float4 wba = wp[(kh_a + 2) * 4 + kw_a];
            float4 wbb = wp[(kh_a + 2) * 4 + kw_a + 2];
            acc[px][0] = fmaf(iaa, waa.x, fmaf(iab, wab.x, fmaf(iba, wba.x, fmaf(ibb, wbb.x, acc[px][0]))));
            acc[px][1] = fmaf(iaa, waa.y, fmaf(iab, wab.y, fmaf(iba, wba.y, fmaf(ibb, wbb.y, acc[px][1]))));
            acc[px][2] = fmaf(iaa, waa.z, fmaf(iab, wab.z, fmaf(iba, wba.z, fmaf(ibb, wbb.z, acc[px][2]))));
            acc[px][3] = fmaf(iaa, waa.w, fmaf(iab, wab.w, fmaf(iba, wba.w, fmaf(ibb, wbb.w, acc[px][3]))));
        }
    }

#pragma unroll
    for (int c = 0; c < 4; c++) {
        int co = co0 + c;
        if (co >= Cout) continue;
        float bv = bias ? bias[co] : 0.f;
        size_t base = (((size_t)n * Cout + co) * Hout + oh) * Wout + c0 + col4;
#pragma unroll
        for (int px = 0; px < 4; px++) {
            float v = acc[px][c] + bv;
            if (out_relu) v = fmaxf(v, 0.f);
            out[base + px] = v;
        }
    }
}

// ================= VQ =================
__global__ void __launch_bounds__(512) vq_kernel(
    const float* __restrict__ Ze, const float* __restrict__ E,
    float* __restrict__ Zq, float* __restrict__ counts, float* __restrict__ loss_sum)
{
    extern __shared__ float Es[];
    __shared__ float e2s[512];
    __shared__ float red[512];
    const int tid = threadIdx.x;

    for (int i = tid * 4; i < 512 * 64; i += 512 * 4)
        *(float4*)&Es[i] = *(const float4*)&E[i];
    __syncthreads();
    {
        const float* er = &Es[tid * 64];
        float s = 0.f;
#pragma unroll
        for (int d = 0; d < 64; d++) s = fmaf(er[d], er[d], s);
        e2s[tid] = s;
    }
    __syncthreads();

    const int vi = blockIdx.x * 512 + tid;
    const int b = vi >> 10;
    const int hw = vi & 1023;
    const float* zp = Ze + (size_t)b * 64 * 1024 + hw;

    float v[64];
    float sv = 0.f;
#pragma unroll
    for (int d = 0; d < 64; d++) {
        v[d] = zp[(size_t)d * 1024];
        sv = fmaf(v[d], v[d], sv);
    }

    float best = 3.402823466e38f;
    int bi = 0;
    for (int k = 0; k < 512; k++) {
        const float4* er = (const float4*)&Es[k * 64];
        float dot = 0.f;
#pragma unroll
        for (int j = 0; j < 16; j++) {
            float4 e = er[j];
            dot = fmaf(v[4 * j + 0], e.x, dot);
            dot = fmaf(v[4 * j + 1], e.y, dot);
            dot = fmaf(v[4 * j + 2], e.z, dot);
            dot = fmaf(v[4 * j + 3], e.w, dot);
        }
        float dist = sv + e2s[k] - 2.f * dot;
        if (dist < best) { best = dist; bi = k; }
    }

    float le = 0.f;
    float* qp = Zq + (size_t)b * 64 * 1024 + hw;
    const float* eb = &Es[bi * 64];
#pragma unroll
    for (int d = 0; d < 64; d++) {
        float q = eb[d];
        qp[(size_t)d * 1024] = q;
        float dd = q - v[d];
        le = fmaf(dd, dd, le);
    }
    atomicAdd(&counts[bi], 1.0f);

    red[tid] = le;
    __syncthreads();
    for (int s = 256; s > 0; s >>= 1) {
        if (tid < s) red[tid] += red[tid + s];
        __syncthreads();
    }
    if (tid == 0) atomicAdd(loss_sum, red[0]);
}

__global__ void zero_small(float* counts, float* loss) {
    int t = blockIdx.x * blockDim.x + threadIdx.x;
    if (t < 512) counts[t] = 0.f;
    if (t == 0) loss[0] = 0.f;
}

__global__ void finalize_kernel(const float* __restrict__ counts,
                                const float* __restrict__ loss_sum,
                                float* __restrict__ out, int out_size) {
    __shared__ float red[512];
    int tid = threadIdx.x;
    float c = counts[tid];
    float p = c * (1.0f / 65536.0f);
    red[tid] = p * log2f(p + 1e-10f);
    __syncthreads();
    for (int s = 256; s > 0; s >>= 1) {
        if (tid < s) red[tid] += red[tid + s];
        __syncthreads();
    }
    if (tid == 0) {
        float ent = -red[0];
        float mse = loss_sum[0] * (1.0f / 4194304.0f);
        out[0] = mse + 0.25f * mse;
        out[out_size - 3] = mse;
        out[out_size - 2] = mse;
        out[out_size - 1] = exp2f(ent);
    }
}

// ================= host launcher =================
extern "C" void kernel_launch(void* const* d_in, const int* in_sizes, int n_in,
                              void* d_out, int out_size) {
    const float* x         = (const float*)d_in[0];
    const float* enc_w1    = (const float*)d_in[1];
    const float* enc_b1    = (const float*)d_in[2];
    const float* enc_w2    = (const float*)d_in[3];
    const float* enc_b2    = (const float*)d_in[4];
    const float* enc_w3    = (const float*)d_in[5];
    const float* enc_b3    = (const float*)d_in[6];
    const float* enc_w4    = (const float*)d_in[7];
    const float* enc_b4    = (const float*)d_in[8];
    const float* enc_res_w1= (const float*)d_in[9];
    const float* enc_res_w2= (const float*)d_in[10];
    const float* enc_adj_w = (const float*)d_in[11];
    const float* enc_adj_b = (const float*)d_in[12];
    const float* E         = (const float*)d_in[13];
    const float* dec_adj_w = (const float*)d_in[14];
    const float* dec_adj_b = (const float*)d_in[15];
    const float* dec_res_w1= (const float*)d_in[16];
    const float* dec_res_w2= (const float*)d_in[17];
    const float* tc1_w     = (const float*)d_in[18];
    const float* tc1_b     = (const float*)d_in[19];
    const float* tc2_w     = (const float*)d_in[20];
    const float* tc2_b     = (const float*)d_in[21];
    float* out = (float*)d_out;

    float *b1, *b2, *b3, *b4, *b5, *wt, *cnt, *lsum;
    cudaGetSymbolAddress((void**)&b1, g_buf1);
    cudaGetSymbolAddress((void**)&b2, g_buf2);
    cudaGetSymbolAddress((void**)&b3, g_buf3);
    cudaGetSymbolAddress((void**)&b4, g_buf4);
    cudaGetSymbolAddress((void**)&b5, g_buf5);
    cudaGetSymbolAddress((void**)&wt, g_wt);
    cudaGetSymbolAddress((void**)&cnt, g_counts);
    cudaGetSymbolAddress((void**)&lsum, g_loss);

    cudaFuncSetAttribute(conv_tc<64, 4, 2, 128, 64>, cudaFuncAttributeMaxDynamicSharedMemorySize, 66560);
    cudaFuncSetAttribute(conv_tc<128, 3, 1, 128, 32>, cudaFuncAttributeMaxDynamicSharedMemorySize, 66560);
    cudaFuncSetAttribute(conv_tc<128, 3, 1, 64, 32>, cudaFuncAttributeMaxDynamicSharedMemorySize, 50176);
    cudaFuncSetAttribute(conv_tc<64, 1, 1, 128, 32>, cudaFuncAttributeMaxDynamicSharedMemorySize, 66560);
    cudaFuncSetAttribute(conv_tc<128, 1, 1, 64, 32>, cudaFuncAttributeMaxDynamicSharedMemorySize, 50176);
    cudaFuncSetAttribute(conv_tc<64, 3, 1, 128, 32>, cudaFuncAttributeMaxDynamicSharedMemorySize, 66560);
    cudaFuncSetAttribute(vq_kernel, cudaFuncAttributeMaxDynamicSharedMemorySize, 131072);

    // weight transposes into g_wt
    wtrans<<<512, 256>>>(enc_w2, wt, 128, 64, 16);
    wtrans<<<576, 256>>>(enc_w3, wt + 131072, 128, 128, 9);
    wtrans<<<576, 256>>>(enc_w4, wt + 278528, 128, 128, 9);
    wtrans<<<288, 256>>>(enc_res_w1, wt + 425984, 64, 128, 9);
    wtrans<<<288, 256>>>(enc_res_w1 + 73728, wt + 499712, 64, 128, 9);
    wtrans<<<288, 256>>>(dec_adj_w, wt + 573440, 128, 64, 9);
    wtrans<<<288, 256>>>(dec_res_w1, wt + 647168, 64, 128, 9);
    wtrans<<<288, 256>>>(dec_res_w1 + 73728, wt + 720896, 64, 128, 9);

    const int B = 64;
    dim3 g8(8, B);

    // -------- encoder --------
    conv_tiled<4, 2, 3><<<dim3(16, B, 4), 256>>>(x, enc_w1, enc_b1, b1,
                                                 64, 128, 128, 64, 64, 1);
    conv_tc<64, 4, 2, 128, 64><<<g8, 256, 66560>>>(b1, wt, enc_b2, nullptr, b2, 0, 1);
    conv_tc<128, 3, 1, 128, 32><<<g8, 256, 66560>>>(b2, wt + 131072, enc_b3, nullptr, b3, 0, 1);
    conv_tc<128, 3, 1, 128, 32><<<g8, 256, 66560>>>(b3, wt + 278528, enc_b4, nullptr, b2, 0, 0);
    conv_tc<128, 3, 1, 64, 32><<<g8, 256, 50176>>>(b2, wt + 425984, nullptr, nullptr, b4, 1, 0);
    conv_tc<64, 1, 1, 128, 32><<<g8, 256, 66560>>>(b4, enc_res_w2, nullptr, b2, b3, 1, 0);
    conv_tc<128, 3, 1, 64, 32><<<g8, 256, 50176>>>(b3, wt + 499712, nullptr, nullptr, b4, 1, 0);
    conv_tc<64, 1, 1, 128, 32><<<g8, 256, 66560>>>(b4, enc_res_w2 + 8192, nullptr, b3, b2, 1, 0);
    conv_tc<128, 1, 1, 64, 32><<<g8, 256, 50176>>>(b2, enc_adj_w, enc_adj_b, nullptr, b5, 1, 0);

    // -------- VQ --------
    zero_small<<<2, 256>>>(cnt, lsum);
    vq_kernel<<<128, 512, 131072>>>(b5, E, b4, cnt, lsum);

    // -------- decoder --------
    conv_tc<64, 3, 1, 128, 32><<<g8, 256, 66560>>>(b4, wt + 573440, dec_adj_b, nullptr, b2, 0, 0);
    conv_tc<128, 3, 1, 64, 32><<<g8, 256, 50176>>>(b2, wt + 647168, nullptr, nullptr, b4, 1, 0);
    conv_tc<64, 1, 1, 128, 32><<<g8, 256, 66560>>>(b4, dec_res_w2, nullptr, b2, b3, 1, 0);
    conv_tc<128, 3, 1, 64, 32><<<g8, 256, 50176>>>(b3, wt + 720896, nullptr, nullptr, b4, 1, 0);
    conv_tc<64, 1, 1, 128, 32><<<g8, 256, 66560>>>(b4, dec_res_w2 + 8192, nullptr, b3, b2, 1, 0);

    convt421<128><<<dim3(16, B, 4), 256>>>(b2, tc1_w, tc1_b, b1,
                                           64, 32, 32, 64, 64, 1, 1);
    convt421<64><<<dim3(1, B, 16), 256>>>(b1, tc2_w, tc2_b, out + 1,
                                          3, 64, 64, 128, 128, 0, 0);

    finalize_kernel<<<1, 512>>>(cnt, lsum, out, out_size);
}

// round 6
// speedup vs baseline: 4.2978x; 1.6627x over previous
#include <cuda_runtime.h>
#include <cuda_bf16.h>
#include <math.h>
#include <stdint.h>

// ---- arch gate: tcgen05 only exists on arch-specific (sm_103a/sm_100a) passes ----
#if defined(__CUDA_ARCH_FEAT_SM103_ALL) || defined(__CUDA_ARCH_FEAT_SM100_ALL) || \
    defined(__CUDA_ARCH_FEAT_SM101_ALL) || defined(__CUDA_ARCH_SPECIFIC__)
#define HAS_TC5 1
#else
#define HAS_TC5 0
#endif

// ================= PTX helpers =================
__device__ __forceinline__ uint32_t smem_u32(const void* p) {
    uint32_t a;
    asm("{ .reg .u64 t; cvta.to.shared.u64 t, %1; cvt.u32.u64 %0, t; }" : "=r"(a) : "l"(p));
    return a;
}
__device__ __forceinline__ uint32_t elect1() {
    uint32_t r;
    asm volatile("{ .reg .pred p; elect.sync _|p, 0xFFFFFFFF; selp.b32 %0, 1, 0, p; }" : "=r"(r));
    return r;
}
__device__ __forceinline__ float tf32r(float x) {
    uint32_t u;
    asm("cvt.rna.tf32.f32 %0, %1;" : "=r"(u) : "f"(x));
    return __uint_as_float(u);
}
__device__ __forceinline__ uint64_t mkdesc(uint32_t addr) {
    const uint64_t BASE = (uint64_t(2) << 61) | (uint64_t(1) << 46) |
                          (uint64_t(64) << 32) | (uint64_t(1) << 16);
    return BASE | ((addr >> 4) & 0x3FFF);
}
#define SWZ(x) ((x) ^ (((x) >> 3) & 0x70))
#define MBAR_INIT(a, n) \
    asm volatile("mbarrier.init.shared.b64 [%0], %1;" :: "r"(a), "r"(n) : "memory")
#define MBAR_WAIT(a, ph) do {                                                      \
    uint32_t _m = (a), _p = (ph), _d;                                              \
    asm volatile("{ .reg .pred p; mbarrier.try_wait.parity.acquire.cta.shared::cta.b64 p, [%1], %2; selp.b32 %0,1,0,p; }" \
                 : "=r"(_d) : "r"(_m), "r"(_p) : "memory");                        \
    if (!_d) {                                                                     \
        asm volatile("{ .reg .pred P1;\n"                                          \
            "W%=: mbarrier.try_wait.parity.acquire.cta.shared::cta.b64 P1, [%0], %1, 0x989680;\n" \
            "@P1 bra.uni D%=;\n bra.uni W%=;\n D%=: }"                             \
            :: "r"(_m), "r"(_p) : "memory");                                       \
    } } while (0)

#if HAS_TC5
#define TC_ALLOC(sa, n)  asm volatile("tcgen05.alloc.cta_group::1.sync.aligned.shared::cta.b32 [%0], %1;" :: "r"(sa), "r"(n) : "memory")
#define TC_DEALLOC(t, n) asm volatile("tcgen05.dealloc.cta_group::1.sync.aligned.b32 %0, %1;" :: "r"(t), "r"(n))
#define TC_RELINQ()      asm volatile("tcgen05.relinquish_alloc_permit.cta_group::1.sync.aligned;")
#define TC_COMMIT(mb)    asm volatile("tcgen05.commit.cta_group::1.mbarrier::arrive::one.shared::cluster.b64 [%0];" :: "r"(mb) : "memory")
#define TC_FENCE_AFTER() asm volatile("tcgen05.fence::after_thread_sync;" ::: "memory")
#define TC_WAIT_LD()     asm volatile("tcgen05.wait::ld.sync.aligned;" ::: "memory")
#define FENCE_ASYNC()    asm volatile("fence.proxy.async.shared::cta;" ::: "memory")

__device__ __forceinline__ void mma_tf32(uint32_t d, uint64_t ad, uint64_t bd,
                                         uint32_t idesc, uint32_t en) {
    asm volatile(
        "{ .reg .pred p; setp.ne.u32 p, %4, 0;\n\t"
        "tcgen05.mma.cta_group::1.kind::tf32 [%0], %1, %2, %3, {%5, %5, %5, %5}, p;\n\t}"
        :: "r"(d), "l"(ad), "l"(bd), "r"(idesc), "r"(en), "r"(0u) : "memory");
}
#define LDTM32(r, ta) \
    asm volatile( \
        "tcgen05.ld.sync.aligned.32x32b.x32.b32 " \
        "{%0,%1,%2,%3,%4,%5,%6,%7,%8,%9,%10,%11,%12,%13,%14,%15," \
        "%16,%17,%18,%19,%20,%21,%22,%23,%24,%25,%26,%27,%28,%29,%30,%31}, [%32];" \
        : "=r"((r)[0]), "=r"((r)[1]), "=r"((r)[2]), "=r"((r)[3]), \
          "=r"((r)[4]), "=r"((r)[5]), "=r"((r)[6]), "=r"((r)[7]), \
          "=r"((r)[8]), "=r"((r)[9]), "=r"((r)[10]), "=r"((r)[11]), \
          "=r"((r)[12]), "=r"((r)[13]), "=r"((r)[14]), "=r"((r)[15]), \
          "=r"((r)[16]), "=r"((r)[17]), "=r"((r)[18]), "=r"((r)[19]), \
          "=r"((r)[20]), "=r"((r)[21]), "=r"((r)[22]), "=r"((r)[23]), \
          "=r"((r)[24]), "=r"((r)[25]), "=r"((r)[26]), "=r"((r)[27]), \
          "=r"((r)[28]), "=r"((r)[29]), "=r"((r)[30]), "=r"((r)[31]) \
        : "r"(ta))
#endif  // HAS_TC5

// ================= scratch =================
__device__ float g_buf1[64 * 64 * 64 * 64];
__device__ float g_buf2[64 * 128 * 32 * 32];
__device__ float g_buf3[64 * 128 * 32 * 32];
__device__ float g_buf4[64 * 64 * 32 * 32];
__device__ float g_buf5[64 * 64 * 32 * 32];
__device__ float g_wt[925696];
__device__ float g_counts[512];
__device__ float g_loss[1];

// ================= weight transform (co,ci,t) -> [co][t][ci] =================
__global__ void wtrans(const float* __restrict__ src, float* __restrict__ dst,
                       int CO, int CI, int T) {
    int i = blockIdx.x * 256 + threadIdx.x;
    if (i < CO * CI * T) {
        int t = i % T;
        int ci = (i / T) % CI;
        int co = i / (T * CI);
        dst[co * CI * T + t * CI + ci] = src[i];
    }
}
// ConvT weights (ci,co,t) -> [co][t][ci]; CI=128, CO=64, T=16
__global__ void wtransT(const float* __restrict__ src, float* __restrict__ dst) {
    int i = blockIdx.x * 256 + threadIdx.x;   // 131072 total
    int t = i & 15;
    int co = (i >> 4) & 63;
    int ci = i >> 10;
    dst[co * 2048 + t * 128 + ci] = src[i];
}

// ================= conv for 32x32 outputs: tcgen05 tf32, scalar fallback =================
template <int CIN, int KSZ, int S, int NCO, int HIN>
__global__ void __launch_bounds__(256) conv_tc(
    const float* __restrict__ in, const float* __restrict__ Bt,
    const float* __restrict__ bias, const float* __restrict__ resid,
    float* __restrict__ out, int in_relu, int out_relu)
{
    constexpr int T = KSZ * KSZ;
    constexpr int P = (KSZ == 1) ? 0 : 1;
    const int tid = threadIdx.x;
    const int mt = blockIdx.x;
    const int n = blockIdx.y;
    const float* inb = in + (size_t)n * CIN * (HIN * HIN);

#if HAS_TC5
    constexpr int GCI = CIN / 32;
    constexpr int NCH = T * GCI;
    constexpr int BB = NCO * 128;
    constexpr uint32_t IDESC =
        (1u << 4) | (2u << 7) | (2u << 10) | ((uint32_t)(NCO / 8) << 17) | (8u << 24);

    extern __shared__ char smem[];
    const uint32_t sb = smem_u32(smem);
    const uint32_t mb0 = sb + 16, mb1 = sb + 24;
    char* Ab = smem + 1024;
    char* Bb = smem + 1024 + 32768;

    const int wid = tid >> 5, lid = tid & 31;

    if (tid == 0) { MBAR_INIT(mb0, 1); MBAR_INIT(mb1, 1); }
    if (wid == 0) { TC_ALLOC(sb, 128); TC_RELINQ(); }
    __syncthreads();
    uint32_t tmem;
    asm volatile("ld.shared.b32 %0, [%1];" : "=r"(tmem) : "r"(sb));

    int ph0 = 0, ph1 = 0;
    for (int c = 0; c < NCH; c++) {
        const int bsel = c & 1;
        if (c >= 2) {
            if (bsel == 0) { MBAR_WAIT(mb0, ph0); ph0 ^= 1; }
            else           { MBAR_WAIT(mb1, ph1); ph1 ^= 1; }
        }
        const int t = c / GCI;
        const int g = c - t * GCI;
        const int kh = t / KSZ, kw = t - kh * KSZ;
        char* A = Ab + bsel * 16384;
        char* B = Bb + bsel * BB;

#pragma unroll
        for (int it = 0; it < 4; it++) {
            int slot = tid + it * 256;
            int jg = slot >> 7;
            int m = slot & 127;
            int oh = (mt << 2) + (m >> 5);
            int ow = m & 31;
            int ih = oh * S - P + kh;
            int iw = ow * S - P + kw;
            float4 v = make_float4(0.f, 0.f, 0.f, 0.f);
            if (ih >= 0 && ih < HIN && iw >= 0 && iw < HIN) {
                const float* p = inb + (size_t)(g * 32 + jg * 4) * (HIN * HIN) + ih * HIN + iw;
                v.x = p[0];
                v.y = p[HIN * HIN];
                v.z = p[2 * HIN * HIN];
                v.w = p[3 * HIN * HIN];
            }
            if (in_relu) {
                v.x = fmaxf(v.x, 0.f); v.y = fmaxf(v.y, 0.f);
                v.z = fmaxf(v.z, 0.f); v.w = fmaxf(v.w, 0.f);
            }
            v.x = tf32r(v.x); v.y = tf32r(v.y); v.z = tf32r(v.z); v.w = tf32r(v.w);
            *(float4*)(A + SWZ(m * 128 + jg * 16)) = v;
        }
#pragma unroll
        for (int it = 0; it < NCO / 32; it++) {
            int slot = tid + it * 256;
            int jg = slot & 7;
            int co = slot >> 3;
            float4 v = *(const float4*)(Bt + (size_t)co * (T * CIN) + t * CIN + g * 32 + jg * 4);
            v.x = tf32r(v.x); v.y = tf32r(v.y); v.z = tf32r(v.z); v.w = tf32r(v.w);
            *(float4*)(B + SWZ(co * 128 + jg * 16)) = v;
        }
        FENCE_ASYNC();
        __syncthreads();
        if (wid == 0 && elect1()) {
            uint32_t aAddr = sb + 1024 + bsel * 16384;
            uint32_t bAddr = sb + 1024 + 32768 + bsel * BB;
            uint64_t ad = mkdesc(aAddr), bd = mkdesc(bAddr);
#pragma unroll
            for (int s2 = 0; s2 < 4; s2++)
                mma_tf32(tmem, ad + s2 * 2, bd + s2 * 2, IDESC, (c > 0 || s2 > 0) ? 1u : 0u);
            TC_COMMIT(bsel ? mb1 : mb0);
        }
    }

    MBAR_WAIT(mb0, ph0);
    MBAR_WAIT(mb1, ph1);
    TC_FENCE_AFTER();

    if (wid < 4) {
        const int p = (mt << 7) + (wid << 5) + lid;
#pragma unroll
        for (int cb = 0; cb < NCO / 32; cb++) {
            uint32_t d[32];
            LDTM32(d, tmem + cb * 32);
            TC_WAIT_LD();
#pragma unroll
            for (int q = 0; q < 32; q++) {
                int co = cb * 32 + q;
                float v = __uint_as_float(d[q]);
                if (bias) v += bias[co];
                size_t o = (((size_t)n * NCO + co) << 10) + p;
                if (resid) v += resid[o];
                if (out_relu) v = fmaxf(v, 0.f);
                out[o] = v;
            }
        }
    }
    __syncthreads();
    if (wid == 0) TC_DEALLOC(tmem, 128);

#else  // ---------- scalar fallback ----------
    constexpr int TIH = 3 * S + KSZ;
    constexpr int TIW = 31 * S + KSZ;
    extern __shared__ float fsm[];
    float* tile = fsm;
    float* wci = fsm + TIH * TIW;

    const int m = tid & 127;
    const int half = tid >> 7;
    const int ohl = m >> 5, ow = m & 31;
    const int rbase = (mt << 2) * S - P;

    float acc[NCO / 2];
#pragma unroll
    for (int j = 0; j < NCO / 2; j++) acc[j] = 0.f;

    for (int ci = 0; ci < CIN; ci++) {
        __syncthreads();
        const float* ip = inb + (size_t)ci * (HIN * HIN);
        for (int i = tid; i < TIH * TIW; i += 256) {
            int tr = i / TIW, tc = i - tr * TIW;
            int gr = rbase + tr, gc = tc - P;
            float v = 0.f;
            if (gr >= 0 && gr < HIN && gc >= 0 && gc < HIN) v = ip[gr * HIN + gc];
            if (in_relu) v = fmaxf(v, 0.f);
            tile[i] = v;
        }
        for (int i = tid; i < T * NCO; i += 256) {
            int t = i / NCO, co = i - t * NCO;
            wci[i] = Bt[(size_t)co * (T * CIN) + t * CIN + ci];
        }
        __syncthreads();
#pragma unroll
        for (int t = 0; t < T; t++) {
            int kh = t / KSZ, kw = t - kh * KSZ;
            float iv = tile[(ohl * S + kh) * TIW + ow * S + kw];
            const float4* wp = (const float4*)(wci + t * NCO + half * (NCO / 2));
#pragma unroll
            for (int j = 0; j < NCO / 8; j++) {
                float4 wv = wp[j];
                acc[4 * j + 0] = fmaf(iv, wv.x, acc[4 * j + 0]);
                acc[4 * j + 1] = fmaf(iv, wv.y, acc[4 * j + 1]);
                acc[4 * j + 2] = fmaf(iv, wv.z, acc[4 * j + 2]);
                acc[4 * j + 3] = fmaf(iv, wv.w, acc[4 * j + 3]);
            }
        }
    }

    const int p = (mt << 7) + m;
#pragma unroll
    for (int j = 0; j < NCO / 2; j++) {
        int co = half * (NCO / 2) + j;
        float v = acc[j];
        if (bias) v += bias[co];
        size_t o = (((size_t)n * NCO + co) << 10) + p;
        if (resid) v += resid[o];
        if (out_relu) v = fmaxf(v, 0.f);
        out[o] = v;
    }
#endif
}

// ================= ConvTranspose tc1 as tcgen05 (parity decomposition) =================
// in: (n,128,32,32) -> out: (n,64,64,64). Bt: [co][kh*4+kw][ci] (64 x 16 x 128).
// grid: (mt 0..7, n, parity 0..3). M=128 px of the (r,c) 32x32 grid, N=64, K=16 chunks.
__global__ void __launch_bounds__(256) convt_tc(
    const float* __restrict__ in, const float* __restrict__ Bt,
    const float* __restrict__ bias, float* __restrict__ out)
{
    const int tid = threadIdx.x;
    const int mt = blockIdx.x;
    const int n = blockIdx.y;
    const int par = blockIdx.z;
    const int po = par >> 1, pw = par & 1;
    const float* inb = in + (size_t)n * 128 * 1024;

#if HAS_TC5
    constexpr uint32_t IDESC = (1u << 4) | (2u << 7) | (2u << 10) | (8u << 17) | (8u << 24);
    extern __shared__ char smem[];
    const uint32_t sb = smem_u32(smem);
    const uint32_t mb0 = sb + 16, mb1 = sb + 24;
    char* Ab = smem + 1024;
    char* Bb = smem + 1024 + 32768;

    const int wid = tid >> 5, lid = tid & 31;

    if (tid == 0) { MBAR_INIT(mb0, 1); MBAR_INIT(mb1, 1); }
    if (wid == 0) { TC_ALLOC(sb, 128); TC_RELINQ(); }
    __syncthreads();
    uint32_t tmem;
    asm volatile("ld.shared.b32 %0, [%1];" : "=r"(tmem) : "r"(sb));

    int ph0 = 0, ph1 = 0;
    for (int c = 0; c < 16; c++) {               // 4 taps x 4 ci-groups
        const int bsel = c & 1;
        if (c >= 2) {
            if (bsel == 0) { MBAR_WAIT(mb0, ph0); ph0 ^= 1; }
            else           { MBAR_WAIT(mb1, ph1); ph1 ^= 1; }
        }
        const int t = c >> 2;                    // tap index 0..3
        const int g = c & 3;                     // ci group
        const int i2 = t >> 1, j2 = t & 1;
        const int dh = po - i2, dw = pw - j2;
        const int kh = (1 - po) + 2 * i2, kw = (1 - pw) + 2 * j2;
        const int tg = kh * 4 + kw;
        char* A = Ab + bsel * 16384;
        char* B = Bb + bsel * 8192;

#pragma unroll
        for (int it = 0; it < 4; it++) {
            int slot = tid + it * 256;
            int jg = slot >> 7;
            int m = slot & 127;
            int r = (mt << 2) + (m >> 5);
            int cc = m & 31;
            int ih = r + dh, iw = cc + dw;
            float4 v = make_float4(0.f, 0.f, 0.f, 0.f);
            if (ih >= 0 && ih < 32 && iw >= 0 && iw < 32) {
                const float* p = inb + (size_t)(g * 32 + jg * 4) * 1024 + ih * 32 + iw;
                v.x = fmaxf(p[0], 0.f);
                v.y = fmaxf(p[1024], 0.f);
                v.z = fmaxf(p[2048], 0.f);
                v.w = fmaxf(p[3072], 0.f);
            }
            v.x = tf32r(v.x); v.y = tf32r(v.y); v.z = tf32r(v.z); v.w = tf32r(v.w);
            *(float4*)(A + SWZ(m * 128 + jg * 16)) = v;
        }
        // B: 64 co rows x 32 ci -> 512 float4 slots / 256 threads = 2 its
#pragma unroll
        for (int it = 0; it < 2; it++) {
            int slot = tid + it * 256;
            int jg = slot & 7;
            int co = slot >> 3;
            float4 v = *(const float4*)(Bt + (size_t)co * 2048 + tg * 128 + g * 32 + jg * 4);
            v.x = tf32r(v.x); v.y = tf32r(v.y); v.z = tf32r(v.z); v.w = tf32r(v.w);
            *(float4*)(B + SWZ(co * 128 + jg * 16)) = v;
        }
        FENCE_ASYNC();
        __syncthreads();
        if (wid == 0 && elect1()) {
            uint64_t ad = mkdesc(sb + 1024 + bsel * 16384);
            uint64_t bd = mkdesc(sb + 1024 + 32768 + bsel * 8192);
#pragma unroll
            for (int s2 = 0; s2 < 4; s2++)
                mma_tf32(tmem, ad + s2 * 2, bd + s2 * 2, IDESC, (c > 0 || s2 > 0) ? 1u : 0u);
            TC_COMMIT(bsel ? mb1 : mb0);
        }
    }

    MBAR_WAIT(mb0, ph0);
    MBAR_WAIT(mb1, ph1);
    TC_FENCE_AFTER();

    if (wid < 4) {
        const int r = (mt << 2) + wid;
        const int oh = 2 * r + po;
        const int ow = 2 * lid + pw;
#pragma unroll
        for (int cb = 0; cb < 2; cb++) {
            uint32_t d[32];
            LDTM32(d, tmem + cb * 32);
            TC_WAIT_LD();
#pragma unroll
            for (int q = 0; q < 32; q++) {
                int co = cb * 32 + q;
                float v = __uint_as_float(d[q]) + bias[co];
                v = fmaxf(v, 0.f);
                out[(((size_t)n * 64 + co) << 12) + oh * 64 + ow] = v;
            }
        }
    }
    __syncthreads();
    if (wid == 0) TC_DEALLOC(tmem, 128);

#else  // ---------- scalar fallback (compile-only path) ----------
    const int m = tid & 127;
    const int half = tid >> 7;
    const int r = (mt << 2) + (m >> 5);
    const int cc = m & 31;
    float acc[32];
#pragma unroll
    for (int j = 0; j < 32; j++) acc[j] = 0.f;
    for (int ci = 0; ci < 128; ci++) {
        const float* ip = inb + (size_t)ci * 1024;
#pragma unroll
        for (int t = 0; t < 4; t++) {
            int i2 = t >> 1, j2 = t & 1;
            int ih = r + po - i2, iw = cc + pw - j2;
            int kh = (1 - po) + 2 * i2, kw = (1 - pw) + 2 * j2;
            float iv = 0.f;
            if (ih >= 0 && ih < 32 && iw >= 0 && iw < 32) iv = fmaxf(ip[ih * 32 + iw], 0.f);
            for (int j = 0; j < 32; j++) {
                int co = half * 32 + j;
                acc[j] = fmaf(iv, Bt[(size_t)co * 2048 + (kh * 4 + kw) * 128 + ci], acc[j]);
            }
        }
    }
    const int oh = 2 * r + po, ow = 2 * cc + pw;
#pragma unroll
    for (int j = 0; j < 32; j++) {
        int co = half * 32 + j;
        float v = fmaxf(acc[j] + bias[co], 0.f);
        out[(((size_t)n * 64 + co) << 12) + oh * 64 + ow] = v;
    }
#endif
}

// ================= scalar conv (conv1: 4x4 s2 CIN=3) =================
template <int K, int S, int CIN>
__global__ void __launch_bounds__(256) conv_tiled(
    const float* __restrict__ in, const float* __restrict__ w,
    const float* __restrict__ bias, float* __restrict__ out,
    int Cout, int Hin, int Win, int Hout, int Wout, int out_relu)
{
    constexpr int P = 1;
    constexpr int TI = 31 * S + K;
    constexpr int TILE_N = TI * TI;
    constexpr int NS = (TILE_N + 255) / 256;
    constexpr int RW = 3 * S + K;

    __shared__ float tile[TILE_N];
    __shared__ float4 wsm[CIN * K * K];

    const int tid = threadIdx.x;
    const int co0 = blockIdx.x * 4;
    const int n = blockIdx.y;
    const int tilesX = Wout >> 5;
    const int ty = blockIdx.z / tilesX, tx = blockIdx.z % tilesX;
    const int r0 = ty * 32, c0 = tx * 32;

    float* wsm_f = (float*)wsm;
#pragma unroll
    for (int c = 0; c < 4; c++) {
        const float* wp = w + (size_t)(co0 + c) * CIN * K * K;
        for (int j = tid; j < CIN * K * K; j += 256)
            wsm_f[j * 4 + c] = wp[j];
    }

    int goff[NS];
#pragma unroll
    for (int s = 0; s < NS; s++) {
        int i = tid + s * 256;
        goff[s] = -1;
        if (i < TILE_N) {
            int tr = i / TI, tc = i % TI;
            int gr = r0 * S - P + tr, gc = c0 * S - P + tc;
            if (gr >= 0 && gr < Hin && gc >= 0 && gc < Win) goff[s] = gr * Win + gc;
        }
    }

    const int row = tid >> 3;
    const int col4 = (tid & 7) << 2;

    float acc[4][4];
#pragma unroll
    for (int a = 0; a < 4; a++)
#pragma unroll
        for (int b = 0; b < 4; b++) acc[a][b] = 0.f;

    const float* inb = in + (size_t)n * CIN * Hin * Win;

    for (int ci = 0; ci < CIN; ci++) {
        __syncthreads();
        const float* ip = inb + (size_t)ci * Hin * Win;
#pragma unroll
        for (int s = 0; s < NS; s++) {
            int i = tid + s * 256;
            if (i < TILE_N) tile[i] = (goff[s] >= 0) ? ip[goff[s]] : 0.f;
        }
        __syncthreads();

        float rg[K][RW];
#pragma unroll
        for (int a = 0; a < K; a++)
#pragma unroll
            for (int b = 0; b < RW; b++)
                rg[a][b] = tile[(row * S + a) * TI + col4 * S + b];

        const float4* wp = wsm + ci * K * K;
#pragma unroll
        for (int kh = 0; kh < K; kh++)
#pragma unroll
            for (int kw = 0; kw < K; kw++) {
                float4 wv = wp[kh * K + kw];
#pragma unroll
                for (int px = 0; px < 4; px++) {
                    float iv = rg[kh][px * S + kw];
                    acc[px][0] = fmaf(iv, wv.x, acc[px][0]);
                    acc[px][1] = fmaf(iv, wv.y, acc[px][1]);
                    acc[px][2] = fmaf(iv, wv.z, acc[px][2]);
                    acc[px][3] = fmaf(iv, wv.w, acc[px][3]);
                }
            }
    }

#pragma unroll
    for (int c = 0; c < 4; c++) {
        int co = co0 + c;
        float bv = bias ? bias[co] : 0.f;
        size_t base = (((size_t)n * Cout + co) * Hout + r0 + row) * Wout + c0 + col4;
#pragma unroll
        for (int px = 0; px < 4; px++) {
            float v = acc[px][c] + bv;
            if (out_relu) v = fmaxf(v, 0.f);
            out[base + px] = v;
        }
    }
}

// ================= ConvTranspose k=4 s=2 p=1, scalar 4co (tc2) =================
template <int CIN>
__global__ void __launch_bounds__(256) convt421(
    const float* __restrict__ in, const float* __restrict__ w,
    const float* __restrict__ bias, float* __restrict__ out,
    int Cout, int Hin, int Win, int Hout, int Wout, int in_relu, int out_relu)
{
    __shared__ float tile[18 * 18];
    __shared__ float4 wsm[CIN * 16];

    const int tid = threadIdx.x;
    const int co0 = blockIdx.x * 4;
    const int n = blockIdx.y;
    const int tilesX = Wout >> 5;
    const int ty = blockIdx.z / tilesX, tx = blockIdx.z % tilesX;
    const int r0 = ty * 32, c0 = tx * 32;
    const int base_i = (r0 >> 1) - 1, base_j = (c0 >> 1) - 1;

    float* wsm_f = (float*)wsm;
#pragma unroll
    for (int c = 0; c < 4; c++) {
        int co = co0 + c;
        for (int j = tid; j < CIN * 16; j += 256)
            wsm_f[j * 4 + c] =
                (co < Cout) ? w[((size_t)(j >> 4) * Cout + co) * 16 + (j & 15)] : 0.f;
    }

    const int row = tid >> 3;
    const int col4 = (tid & 7) << 2;
    const int oh = r0 + row;
    const int kh_a = (oh + 1) & 1;
    const int ta = ((oh + 1 - kh_a) >> 1) - base_i;
    const int tb = ta - 1;

    float acc[4][4];
#pragma unroll
    for (int a = 0; a < 4; a++)
#pragma unroll
        for (int b = 0; b < 4; b++) acc[a][b] = 0.f;

    const float* inb = in + (size_t)n * CIN * Hin * Win;

    for (int ci = 0; ci < CIN; ci++) {
        __syncthreads();
        for (int i = tid; i < 324; i += 256) {
            int tr = i / 18, tc = i % 18;
            int gi = base_i + tr, gj = base_j + tc;
            float v = 0.f;
            if (gi >= 0 && gi < Hin && gj >= 0 && gj < Win)
                v = inb[((size_t)ci * Hin + gi) * Win + gj];
            if (in_relu) v = fmaxf(v, 0.f);
            tile[i] = v;
        }
        __syncthreads();

        const float4* wp = wsm + ci * 16;
#pragma unroll
        for (int px = 0; px < 4; px++) {
            int ow = c0 + col4 + px;
            int kw_a = (ow + 1) & 1;
            int ja = ((ow + 1 - kw_a) >> 1) - base_j;
            int jb = ja - 1;
            float iaa = tile[ta * 18 + ja], iab = tile[ta * 18 + jb];
            float iba = tile[tb * 18 + ja], ibb = tile[tb * 18 + jb];
            float4 waa = wp[kh_a * 4 + kw_a];
            float4 wab = wp[kh_a * 4 + kw_a + 2];
            float4 wba = wp[(kh_a + 2) * 4 + kw_a];
            float4 wbb = wp[(kh_a + 2) * 4 + kw_a + 2];
            acc[px][0] = fmaf(iaa, waa.x, fmaf(iab, wab.x, fmaf(iba, wba.x, fmaf(ibb, wbb.x, acc[px][0]))));
            acc[px][1] = fmaf(iaa, waa.y, fmaf(iab, wab.y, fmaf(iba, wba.y, fmaf(ibb, wbb.y, acc[px][1]))));
            acc[px][2] = fmaf(iaa, waa.z, fmaf(iab, wab.z, fmaf(iba, wba.z, fmaf(ibb, wbb.z, acc[px][2]))));
            acc[px][3] = fmaf(iaa, waa.w, fmaf(iab, wab.w, fmaf(iba, wba.w, fmaf(ibb, wbb.w, acc[px][3]))));
        }
    }

#pragma unroll
    for (int c = 0; c < 4; c++) {
        int co = co0 + c;
        if (co >= Cout) continue;
        float bv = bias ? bias[co] : 0.f;
        size_t base = (((size_t)n * Cout + co) * Hout + oh) * Wout + c0 + col4;
#pragma unroll
        for (int px = 0; px < 4; px++) {
            float v = acc[px][c] + bv;
            if (out_relu) v = fmaxf(v, 0.f);
            out[base + px] = v;
        }
    }
}

// ================= VQ =================
__global__ void __launch_bounds__(512) vq_kernel(
    const float* __restrict__ Ze, const float* __restrict__ E,
    float* __restrict__ Zq, float* __restrict__ counts, float* __restrict__ loss_sum)
{
    extern __shared__ float Es[];
    __shared__ float e2s[512];
    __shared__ float red[512];
    const int tid = threadIdx.x;

    for (int i = tid * 4; i < 512 * 64; i += 512 * 4)
        *(float4*)&Es[i] = *(const float4*)&E[i];
    __syncthreads();
    {
        const float* er = &Es[tid * 64];
        float s = 0.f;
#pragma unroll
        for (int d = 0; d < 64; d++) s = fmaf(er[d], er[d], s);
        e2s[tid] = s;
    }
    __syncthreads();

    const int vi = blockIdx.x * 512 + tid;
    const int b = vi >> 10;
    const int hw = vi & 1023;
    const float* zp = Ze + (size_t)b * 64 * 1024 + hw;

    float v[64];
    float sv = 0.f;
#pragma unroll
    for (int d = 0; d < 64; d++) {
        v[d] = zp[(size_t)d * 1024];
        sv = fmaf(v[d], v[d], sv);
    }

    float best = 3.402823466e38f;
    int bi = 0;
    for (int k = 0; k < 512; k++) {
        const float4* er = (const float4*)&Es[k * 64];
        float dot = 0.f;
#pragma unroll
        for (int j = 0; j < 16; j++) {
            float4 e = er[j];
            dot = fmaf(v[4 * j + 0], e.x, dot);
            dot = fmaf(v[4 * j + 1], e.y, dot);
            dot = fmaf(v[4 * j + 2], e.z, dot);
            dot = fmaf(v[4 * j + 3], e.w, dot);
        }
        float dist = sv + e2s[k] - 2.f * dot;
        if (dist < best) { best = dist; bi = k; }
    }

    float le = 0.f;
    float* qp = Zq + (size_t)b * 64 * 1024 + hw;
    const float* eb = &Es[bi * 64];
#pragma unroll
    for (int d = 0; d < 64; d++) {
        float q = eb[d];
        qp[(size_t)d * 1024] = q;
        float dd = q - v[d];
        le = fmaf(dd, dd, le);
    }
    atomicAdd(&counts[bi], 1.0f);

    red[tid] = le;
    __syncthreads();
    for (int s = 256; s > 0; s >>= 1) {
        if (tid < s) red[tid] += red[tid + s];
        __syncthreads();
    }
    if (tid == 0) atomicAdd(loss_sum, red[0]);
}

__global__ void zero_small(float* counts, float* loss) {
    int t = blockIdx.x * blockDim.x + threadIdx.x;
    if (t < 512) counts[t] = 0.f;
    if (t == 0) loss[0] = 0.f;
}

__global__ void finalize_kernel(const float* __restrict__ counts,
                                const float* __restrict__ loss_sum,
                                float* __restrict__ out, int out_size) {
    __shared__ float red[512];
    int tid = threadIdx.x;
    float c = counts[tid];
    float p = c * (1.0f / 65536.0f);
    red[tid] = p * log2f(p + 1e-10f);
    __syncthreads();
    for (int s = 256; s > 0; s >>= 1) {
        if (tid < s) red[tid] += red[tid + s];
        __syncthreads();
    }
    if (tid == 0) {
        float ent = -red[0];
        float mse = loss_sum[0] * (1.0f / 4194304.0f);
        out[0] = mse + 0.25f * mse;
        out[out_size - 3] = mse;
        out[out_size - 2] = mse;
        out[out_size - 1] = exp2f(ent);
    }
}

// ================= host launcher =================
extern "C" void kernel_launch(void* const* d_in, const int* in_sizes, int n_in,
                              void* d_out, int out_size) {
    const float* x         = (const float*)d_in[0];
    const float* enc_w1    = (const float*)d_in[1];
    const float* enc_b1    = (const float*)d_in[2];
    const float* enc_w2    = (const float*)d_in[3];
    const float* enc_b2    = (const float*)d_in[4];
    const float* enc_w3    = (const float*)d_in[5];
    const float* enc_b3    = (const float*)d_in[6];
    const float* enc_w4    = (const float*)d_in[7];
    const float* enc_b4    = (const float*)d_in[8];
    const float* enc_res_w1= (const float*)d_in[9];
    const float* enc_res_w2= (const float*)d_in[10];
    const float* enc_adj_w = (const float*)d_in[11];
    const float* enc_adj_b = (const float*)d_in[12];
    const float* E         = (const float*)d_in[13];
    const float* dec_adj_w = (const float*)d_in[14];
    const float* dec_adj_b = (const float*)d_in[15];
    const float* dec_res_w1= (const float*)d_in[16];
    const float* dec_res_w2= (const float*)d_in[17];
    const float* tc1_w     = (const float*)d_in[18];
    const float* tc1_b     = (const float*)d_in[19];
    const float* tc2_w     = (const float*)d_in[20];
    const float* tc2_b     = (const float*)d_in[21];
    float* out = (float*)d_out;

    float *b1, *b2, *b3, *b4, *b5, *wt, *cnt, *lsum;
    cudaGetSymbolAddress((void**)&b1, g_buf1);
    cudaGetSymbolAddress((void**)&b2, g_buf2);
    cudaGetSymbolAddress((void**)&b3, g_buf3);
    cudaGetSymbolAddress((void**)&b4, g_buf4);
    cudaGetSymbolAddress((void**)&b5, g_buf5);
    cudaGetSymbolAddress((void**)&wt, g_wt);
    cudaGetSymbolAddress((void**)&cnt, g_counts);
    cudaGetSymbolAddress((void**)&lsum, g_loss);

    cudaFuncSetAttribute(conv_tc<64, 4, 2, 128, 64>, cudaFuncAttributeMaxDynamicSharedMemorySize, 66560);
    cudaFuncSetAttribute(conv_tc<128, 3, 1, 128, 32>, cudaFuncAttributeMaxDynamicSharedMemorySize, 66560);
    cudaFuncSetAttribute(conv_tc<128, 3, 1, 64, 32>, cudaFuncAttributeMaxDynamicSharedMemorySize, 50176);
    cudaFuncSetAttribute(conv_tc<64, 1, 1, 128, 32>, cudaFuncAttributeMaxDynamicSharedMemorySize, 66560);
    cudaFuncSetAttribute(conv_tc<128, 1, 1, 64, 32>, cudaFuncAttributeMaxDynamicSharedMemorySize, 50176);
    cudaFuncSetAttribute(conv_tc<64, 3, 1, 128, 32>, cudaFuncAttributeMaxDynamicSharedMemorySize, 66560);
    cudaFuncSetAttribute(convt_tc, cudaFuncAttributeMaxDynamicSharedMemorySize, 50176);
    cudaFuncSetAttribute(vq_kernel, cudaFuncAttributeMaxDynamicSharedMemorySize, 131072);

    // weight transposes into g_wt
    wtrans<<<512, 256>>>(enc_w2, wt, 128, 64, 16);
    wtrans<<<576, 256>>>(enc_w3, wt + 131072, 128, 128, 9);
    wtrans<<<576, 256>>>(enc_w4, wt + 278528, 128, 128, 9);
    wtrans<<<288, 256>>>(enc_res_w1, wt + 425984, 64, 128, 9);
    wtrans<<<288, 256>>>(enc_res_w1 + 73728, wt + 499712, 64, 128, 9);
    wtrans<<<288, 256>>>(dec_adj_w, wt + 573440, 128, 64, 9);
    wtrans<<<288, 256>>>(dec_res_w1, wt + 647168, 64, 128, 9);
    wtrans<<<288, 256>>>(dec_res_w1 + 73728, wt + 720896, 64, 128, 9);
    wtransT<<<512, 256>>>(tc1_w, wt + 794624);

    const int B = 64;
    dim3 g8(8, B);

    // -------- encoder --------
    conv_tiled<4, 2, 3><<<dim3(16, B, 4), 256>>>(x, enc_w1, enc_b1, b1,
                                                 64, 128, 128, 64, 64, 1);
    conv_tc<64, 4, 2, 128, 64><<<g8, 256, 66560>>>(b1, wt, enc_b2, nullptr, b2, 0, 1);
    conv_tc<128, 3, 1, 128, 32><<<g8, 256, 66560>>>(b2, wt + 131072, enc_b3, nullptr, b3, 0, 1);
    conv_tc<128, 3, 1, 128, 32><<<g8, 256, 66560>>>(b3, wt + 278528, enc_b4, nullptr, b2, 0, 0);
    conv_tc<128, 3, 1, 64, 32><<<g8, 256, 50176>>>(b2, wt + 425984, nullptr, nullptr, b4, 1, 0);
    conv_tc<64, 1, 1, 128, 32><<<g8, 256, 66560>>>(b4, enc_res_w2, nullptr, b2, b3, 1, 0);
    conv_tc<128, 3, 1, 64, 32><<<g8, 256, 50176>>>(b3, wt + 499712, nullptr, nullptr, b4, 1, 0);
    conv_tc<64, 1, 1, 128, 32><<<g8, 256, 66560>>>(b4, enc_res_w2 + 8192, nullptr, b3, b2, 1, 0);
    conv_tc<128, 1, 1, 64, 32><<<g8, 256, 50176>>>(b2, enc_adj_w, enc_adj_b, nullptr, b5, 1, 0);

    // -------- VQ --------
    zero_small<<<2, 256>>>(cnt, lsum);
    vq_kernel<<<128, 512, 131072>>>(b5, E, b4, cnt, lsum);

    // -------- decoder --------
    conv_tc<64, 3, 1, 128, 32><<<g8, 256, 66560>>>(b4, wt + 573440, dec_adj_b, nullptr, b2, 0, 0);
    conv_tc<128, 3, 1, 64, 32><<<g8, 256, 50176>>>(b2, wt + 647168, nullptr, nullptr, b4, 1, 0);
    conv_tc<64, 1, 1, 128, 32><<<g8, 256, 66560>>>(b4, dec_res_w2, nullptr, b2, b3, 1, 0);
    conv_tc<128, 3, 1, 64, 32><<<g8, 256, 50176>>>(b3, wt + 720896, nullptr, nullptr, b4, 1, 0);
    conv_tc<64, 1, 1, 128, 32><<<g8, 256, 66560>>>(b4, dec_res_w2 + 8192, nullptr, b3, b2, 1, 0);

    // tc1 via tcgen05 parity decomposition (input relu fused)
    convt_tc<<<dim3(8, B, 4), 256, 50176>>>(b2, wt + 794624, tc1_b, b1);
    convt421<64><<<dim3(1, B, 16), 256>>>(b1, tc2_w, tc2_b, out + 1,
                                          3, 64, 64, 128, 128, 0, 0);

    finalize_kernel<<<1, 512>>>(cnt, lsum, out, out_size);
}

// round 7
// speedup vs baseline: 4.8194x; 1.1214x over previous
#include <cuda_runtime.h>
#include <cuda_bf16.h>
#include <math.h>
#include <stdint.h>

// ---- arch gate ----
#if defined(__CUDA_ARCH_FEAT_SM103_ALL) || defined(__CUDA_ARCH_FEAT_SM100_ALL) || \
    defined(__CUDA_ARCH_FEAT_SM101_ALL) || defined(__CUDA_ARCH_SPECIFIC__)
#define HAS_TC5 1
#else
#define HAS_TC5 0
#endif

// ================= PTX helpers =================
__device__ __forceinline__ uint32_t smem_u32(const void* p) {
    uint32_t a;
    asm("{ .reg .u64 t; cvta.to.shared.u64 t, %1; cvt.u32.u64 %0, t; }" : "=r"(a) : "l"(p));
    return a;
}
__device__ __forceinline__ uint32_t elect1() {
    uint32_t r;
    asm volatile("{ .reg .pred p; elect.sync _|p, 0xFFFFFFFF; selp.b32 %0, 1, 0, p; }" : "=r"(r));
    return r;
}
__device__ __forceinline__ float tf32r(float x) {
    uint32_t u;
    asm("cvt.rna.tf32.f32 %0, %1;" : "=r"(u) : "f"(x));
    return __uint_as_float(u);
}
__device__ __forceinline__ uint64_t mkdesc(uint32_t addr) {
    const uint64_t BASE = (uint64_t(2) << 61) | (uint64_t(1) << 46) |
                          (uint64_t(64) << 32) | (uint64_t(1) << 16);
    return BASE | ((addr >> 4) & 0x3FFF);
}
#define SWZ(x) ((x) ^ (((x) >> 3) & 0x70))
#define MBAR_INIT(a, n) \
    asm volatile("mbarrier.init.shared.b64 [%0], %1;" :: "r"(a), "r"(n) : "memory")
#define MBAR_WAIT(a, ph) do {                                                      \
    uint32_t _m = (a), _p = (ph), _d;                                              \
    asm volatile("{ .reg .pred p; mbarrier.try_wait.parity.acquire.cta.shared::cta.b64 p, [%1], %2; selp.b32 %0,1,0,p; }" \
                 : "=r"(_d) : "r"(_m), "r"(_p) : "memory");                        \
    if (!_d) {                                                                     \
        asm volatile("{ .reg .pred P1;\n"                                          \
            "W%=: mbarrier.try_wait.parity.acquire.cta.shared::cta.b64 P1, [%0], %1, 0x989680;\n" \
            "@P1 bra.uni D%=;\n bra.uni W%=;\n D%=: }"                             \
            :: "r"(_m), "r"(_p) : "memory");                                       \
    } } while (0)

#if HAS_TC5
#define TC_ALLOC(sa, n)  asm volatile("tcgen05.alloc.cta_group::1.sync.aligned.shared::cta.b32 [%0], %1;" :: "r"(sa), "r"(n) : "memory")
#define TC_DEALLOC(t, n) asm volatile("tcgen05.dealloc.cta_group::1.sync.aligned.b32 %0, %1;" :: "r"(t), "r"(n))
#define TC_RELINQ()      asm volatile("tcgen05.relinquish_alloc_permit.cta_group::1.sync.aligned;")
#define TC_COMMIT(mb)    asm volatile("tcgen05.commit.cta_group::1.mbarrier::arrive::one.shared::cluster.b64 [%0];" :: "r"(mb) : "memory")
#define TC_FENCE_AFTER() asm volatile("tcgen05.fence::after_thread_sync;" ::: "memory")
#define TC_WAIT_LD()     asm volatile("tcgen05.wait::ld.sync.aligned;" ::: "memory")
#define FENCE_ASYNC()    asm volatile("fence.proxy.async.shared::cta;" ::: "memory")

__device__ __forceinline__ void mma_tf32(uint32_t d, uint64_t ad, uint64_t bd,
                                         uint32_t idesc, uint32_t en) {
    asm volatile(
        "{ .reg .pred p; setp.ne.u32 p, %4, 0;\n\t"
        "tcgen05.mma.cta_group::1.kind::tf32 [%0], %1, %2, %3, {%5, %5, %5, %5}, p;\n\t}"
        :: "r"(d), "l"(ad), "l"(bd), "r"(idesc), "r"(en), "r"(0u) : "memory");
}
#define LDTM32(r, ta) \
    asm volatile( \
        "tcgen05.ld.sync.aligned.32x32b.x32.b32 " \
        "{%0,%1,%2,%3,%4,%5,%6,%7,%8,%9,%10,%11,%12,%13,%14,%15," \
        "%16,%17,%18,%19,%20,%21,%22,%23,%24,%25,%26,%27,%28,%29,%30,%31}, [%32];" \
        : "=r"((r)[0]), "=r"((r)[1]), "=r"((r)[2]), "=r"((r)[3]), \
          "=r"((r)[4]), "=r"((r)[5]), "=r"((r)[6]), "=r"((r)[7]), \
          "=r"((r)[8]), "=r"((r)[9]), "=r"((r)[10]), "=r"((r)[11]), \
          "=r"((r)[12]), "=r"((r)[13]), "=r"((r)[14]), "=r"((r)[15]), \
          "=r"((r)[16]), "=r"((r)[17]), "=r"((r)[18]), "=r"((r)[19]), \
          "=r"((r)[20]), "=r"((r)[21]), "=r"((r)[22]), "=r"((r)[23]), \
          "=r"((r)[24]), "=r"((r)[25]), "=r"((r)[26]), "=r"((r)[27]), \
          "=r"((r)[28]), "=r"((r)[29]), "=r"((r)[30]), "=r"((r)[31]) \
        : "r"(ta))
#endif  // HAS_TC5

// ================= scratch =================
__device__ float g_buf1[64 * 64 * 64 * 64];
__device__ float g_buf2[64 * 128 * 32 * 32];
__device__ float g_buf3[64 * 128 * 32 * 32];
__device__ float g_buf4[64 * 64 * 32 * 32];
__device__ float g_buf5[64 * 64 * 32 * 32];
__device__ float g_wt[925696];
__device__ float g_counts[512];
__device__ float g_loss[1];

// ================= merged weight transform =================
__global__ void wtrans_all(
    const float* __restrict__ enc_w2, const float* __restrict__ enc_w3,
    const float* __restrict__ enc_w4, const float* __restrict__ enc_res_w1,
    const float* __restrict__ dec_adj_w, const float* __restrict__ dec_res_w1,
    const float* __restrict__ tc1_w, float* __restrict__ wt)
{
    int i = blockIdx.x * 256 + threadIdx.x;
    if (i < 131072) {                         // enc_w2 CO128 CI64 T16
        int t = i % 16, ci = (i / 16) % 64, co = i / 1024;
        wt[co * 1024 + t * 64 + ci] = enc_w2[i];
    } else if (i < 278528) { i -= 131072;     // enc_w3 128,128,9
        int t = i % 9, ci = (i / 9) % 128, co = i / 1152;
        wt[131072 + co * 1152 + t * 128 + ci] = enc_w3[i];
    } else if (i < 425984) { i -= 278528;     // enc_w4
        int t = i % 9, ci = (i / 9) % 128, co = i / 1152;
        wt[278528 + co * 1152 + t * 128 + ci] = enc_w4[i];
    } else if (i < 573440) { i -= 425984;     // enc_res_w1 x2: 64,128,9 each
        int t = i % 9, ci = (i / 9) % 128, co = (i / 1152) % 64, blk = i / 73728;
        wt[425984 + blk * 73728 + co * 1152 + t * 128 + ci] = enc_res_w1[i];
    } else if (i < 647168) { i -= 573440;     // dec_adj 128,64,9
        int t = i % 9, ci = (i / 9) % 64, co = i / 576;
        wt[573440 + co * 576 + t * 64 + ci] = dec_adj_w[i];
    } else if (i < 794624) { i -= 647168;     // dec_res_w1 x2
        int t = i % 9, ci = (i / 9) % 128, co = (i / 1152) % 64, blk = i / 73728;
        wt[647168 + blk * 73728 + co * 1152 + t * 128 + ci] = dec_res_w1[i];
    } else if (i < 925696) { i -= 794624;     // tc1 (ci128,co64,t16) -> [co][t][ci]
        int t = i & 15, co = (i >> 4) & 63, ci = i >> 10;
        wt[794624 + co * 2048 + t * 128 + ci] = tc1_w[i];
    }
}

// ================= conv for 32x32 outputs: tcgen05 tf32, scalar fallback =================
template <int CIN, int KSZ, int S, int NCO, int HIN>
__global__ void __launch_bounds__(256) conv_tc(
    const float* __restrict__ in, const float* __restrict__ Bt,
    const float* __restrict__ bias, const float* __restrict__ resid,
    float* __restrict__ out, int in_relu, int out_relu)
{
    constexpr int T = KSZ * KSZ;
    constexpr int P = (KSZ == 1) ? 0 : 1;
    const int tid = threadIdx.x;
    const int mt = blockIdx.x;
    const int n = blockIdx.y;
    const float* inb = in + (size_t)n * CIN * (HIN * HIN);

#if HAS_TC5
    constexpr int GCI = CIN / 32;
    constexpr int NCH = T * GCI;
    constexpr int BB = NCO * 128;
    constexpr uint32_t IDESC =
        (1u << 4) | (2u << 7) | (2u << 10) | ((uint32_t)(NCO / 8) << 17) | (8u << 24);

    extern __shared__ char smem[];
    const uint32_t sb = smem_u32(smem);
    const uint32_t mb0 = sb + 16, mb1 = sb + 24;
    char* Ab = smem + 1024;
    char* Bb = smem + 1024 + 32768;

    const int wid = tid >> 5, lid = tid & 31;

    if (tid == 0) { MBAR_INIT(mb0, 1); MBAR_INIT(mb1, 1); }
    if (wid == 0) { TC_ALLOC(sb, 128); TC_RELINQ(); }
    __syncthreads();
    uint32_t tmem;
    asm volatile("ld.shared.b32 %0, [%1];" : "=r"(tmem) : "r"(sb));

    int ph0 = 0, ph1 = 0;
    for (int c = 0; c < NCH; c++) {
        const int bsel = c & 1;
        if (c >= 2) {
            if (bsel == 0) { MBAR_WAIT(mb0, ph0); ph0 ^= 1; }
            else           { MBAR_WAIT(mb1, ph1); ph1 ^= 1; }
        }
        const int t = c / GCI;
        const int g = c - t * GCI;
        const int kh = t / KSZ, kw = t - kh * KSZ;
        char* A = Ab + bsel * 16384;
        char* B = Bb + bsel * BB;

#pragma unroll
        for (int it = 0; it < 4; it++) {
            int slot = tid + it * 256;
            int jg = slot >> 7;
            int m = slot & 127;
            int oh = (mt << 2) + (m >> 5);
            int ow = m & 31;
            int ih = oh * S - P + kh;
            int iw = ow * S - P + kw;
            float4 v = make_float4(0.f, 0.f, 0.f, 0.f);
            if (ih >= 0 && ih < HIN && iw >= 0 && iw < HIN) {
                const float* p = inb + (size_t)(g * 32 + jg * 4) * (HIN * HIN) + ih * HIN + iw;
                v.x = p[0];
                v.y = p[HIN * HIN];
                v.z = p[2 * HIN * HIN];
                v.w = p[3 * HIN * HIN];
            }
            if (in_relu) {
                v.x = fmaxf(v.x, 0.f); v.y = fmaxf(v.y, 0.f);
                v.z = fmaxf(v.z, 0.f); v.w = fmaxf(v.w, 0.f);
            }
            v.x = tf32r(v.x); v.y = tf32r(v.y); v.z = tf32r(v.z); v.w = tf32r(v.w);
            *(float4*)(A + SWZ(m * 128 + jg * 16)) = v;
        }
#pragma unroll
        for (int it = 0; it < NCO / 32; it++) {
            int slot = tid + it * 256;
            int jg = slot & 7;
            int co = slot >> 3;
            float4 v = *(const float4*)(Bt + (size_t)co * (T * CIN) + t * CIN + g * 32 + jg * 4);
            v.x = tf32r(v.x); v.y = tf32r(v.y); v.z = tf32r(v.z); v.w = tf32r(v.w);
            *(float4*)(B + SWZ(co * 128 + jg * 16)) = v;
        }
        FENCE_ASYNC();
        __syncthreads();
        if (wid == 0 && elect1()) {
            uint32_t aAddr = sb + 1024 + bsel * 16384;
            uint32_t bAddr = sb + 1024 + 32768 + bsel * BB;
            uint64_t ad = mkdesc(aAddr), bd = mkdesc(bAddr);
#pragma unroll
            for (int s2 = 0; s2 < 4; s2++)
                mma_tf32(tmem, ad + s2 * 2, bd + s2 * 2, IDESC, (c > 0 || s2 > 0) ? 1u : 0u);
            TC_COMMIT(bsel ? mb1 : mb0);
        }
    }

    MBAR_WAIT(mb0, ph0);
    MBAR_WAIT(mb1, ph1);
    TC_FENCE_AFTER();

    if (wid < 4) {
        const int p = (mt << 7) + (wid << 5) + lid;
#pragma unroll
        for (int cb = 0; cb < NCO / 32; cb++) {
            uint32_t d[32];
            LDTM32(d, tmem + cb * 32);
            TC_WAIT_LD();
#pragma unroll
            for (int q = 0; q < 32; q++) {
                int co = cb * 32 + q;
                float v = __uint_as_float(d[q]);
                if (bias) v += bias[co];
                size_t o = (((size_t)n * NCO + co) << 10) + p;
                if (resid) v += resid[o];
                if (out_relu) v = fmaxf(v, 0.f);
                out[o] = v;
            }
        }
    }
    __syncthreads();
    if (wid == 0) TC_DEALLOC(tmem, 128);

#else  // ---------- scalar fallback ----------
    constexpr int TIH = 3 * S + KSZ;
    constexpr int TIW = 31 * S + KSZ;
    extern __shared__ float fsm[];
    float* tile = fsm;
    float* wci = fsm + TIH * TIW;

    const int m = tid & 127;
    const int half = tid >> 7;
    const int ohl = m >> 5, ow = m & 31;
    const int rbase = (mt << 2) * S - P;

    float acc[NCO / 2];
#pragma unroll
    for (int j = 0; j < NCO / 2; j++) acc[j] = 0.f;

    for (int ci = 0; ci < CIN; ci++) {
        __syncthreads();
        const float* ip = inb + (size_t)ci * (HIN * HIN);
        for (int i = tid; i < TIH * TIW; i += 256) {
            int tr = i / TIW, tc = i - tr * TIW;
            int gr = rbase + tr, gc = tc - P;
            float v = 0.f;
            if (gr >= 0 && gr < HIN && gc >= 0 && gc < HIN) v = ip[gr * HIN + gc];
            if (in_relu) v = fmaxf(v, 0.f);
            tile[i] = v;
        }
        for (int i = tid; i < T * NCO; i += 256) {
            int t = i / NCO, co = i - t * NCO;
            wci[i] = Bt[(size_t)co * (T * CIN) + t * CIN + ci];
        }
        __syncthreads();
#pragma unroll
        for (int t = 0; t < T; t++) {
            int kh = t / KSZ, kw = t - kh * KSZ;
            float iv = tile[(ohl * S + kh) * TIW + ow * S + kw];
            const float4* wp = (const float4*)(wci + t * NCO + half * (NCO / 2));
#pragma unroll
            for (int j = 0; j < NCO / 8; j++) {
                float4 wv = wp[j];
                acc[4 * j + 0] = fmaf(iv, wv.x, acc[4 * j + 0]);
                acc[4 * j + 1] = fmaf(iv, wv.y, acc[4 * j + 1]);
                acc[4 * j + 2] = fmaf(iv, wv.z, acc[4 * j + 2]);
                acc[4 * j + 3] = fmaf(iv, wv.w, acc[4 * j + 3]);
            }
        }
    }

    const int p = (mt << 7) + m;
#pragma unroll
    for (int j = 0; j < NCO / 2; j++) {
        int co = half * (NCO / 2) + j;
        float v = acc[j];
        if (bias) v += bias[co];
        size_t o = (((size_t)n * NCO + co) << 10) + p;
        if (resid) v += resid[o];
        if (out_relu) v = fmaxf(v, 0.f);
        out[o] = v;
    }
#endif
}

// ================= ConvTranspose tc1 as tcgen05 (parity decomposition) =================
__global__ void __launch_bounds__(256) convt_tc(
    const float* __restrict__ in, const float* __restrict__ Bt,
    const float* __restrict__ bias, float* __restrict__ out)
{
    const int tid = threadIdx.x;
    const int mt = blockIdx.x;
    const int n = blockIdx.y;
    const int par = blockIdx.z;
    const int po = par >> 1, pw = par & 1;
    const float* inb = in + (size_t)n * 128 * 1024;

#if HAS_TC5
    constexpr uint32_t IDESC = (1u << 4) | (2u << 7) | (2u << 10) | (8u << 17) | (8u << 24);
    extern __shared__ char smem[];
    const uint32_t sb = smem_u32(smem);
    const uint32_t mb0 = sb + 16, mb1 = sb + 24;
    char* Ab = smem + 1024;
    char* Bb = smem + 1024 + 32768;

    const int wid = tid >> 5, lid = tid & 31;

    if (tid == 0) { MBAR_INIT(mb0, 1); MBAR_INIT(mb1, 1); }
    if (wid == 0) { TC_ALLOC(sb, 128); TC_RELINQ(); }
    __syncthreads();
    uint32_t tmem;
    asm volatile("ld.shared.b32 %0, [%1];" : "=r"(tmem) : "r"(sb));

    int ph0 = 0, ph1 = 0;
    for (int c = 0; c < 16; c++) {
        const int bsel = c & 1;
        if (c >= 2) {
            if (bsel == 0) { MBAR_WAIT(mb0, ph0); ph0 ^= 1; }
            else           { MBAR_WAIT(mb1, ph1); ph1 ^= 1; }
        }
        const int t = c >> 2;
        const int g = c & 3;
        const int i2 = t >> 1, j2 = t & 1;
        const int dh = po - i2, dw = pw - j2;
        const int kh = (1 - po) + 2 * i2, kw = (1 - pw) + 2 * j2;
        const int tg = kh * 4 + kw;
        char* A = Ab + bsel * 16384;
        char* B = Bb + bsel * 8192;

#pragma unroll
        for (int it = 0; it < 4; it++) {
            int slot = tid + it * 256;
            int jg = slot >> 7;
            int m = slot & 127;
            int r = (mt << 2) + (m >> 5);
            int cc = m & 31;
            int ih = r + dh, iw = cc + dw;
            float4 v = make_float4(0.f, 0.f, 0.f, 0.f);
            if (ih >= 0 && ih < 32 && iw >= 0 && iw < 32) {
                const float* p = inb + (size_t)(g * 32 + jg * 4) * 1024 + ih * 32 + iw;
                v.x = fmaxf(p[0], 0.f);
                v.y = fmaxf(p[1024], 0.f);
                v.z = fmaxf(p[2048], 0.f);
                v.w = fmaxf(p[3072], 0.f);
            }
            v.x = tf32r(v.x); v.y = tf32r(v.y); v.z = tf32r(v.z); v.w = tf32r(v.w);
            *(float4*)(A + SWZ(m * 128 + jg * 16)) = v;
        }
#pragma unroll
        for (int it = 0; it < 2; it++) {
            int slot = tid + it * 256;
            int jg = slot & 7;
            int co = slot >> 3;
            float4 v = *(const float4*)(Bt + (size_t)co * 2048 + tg * 128 + g * 32 + jg * 4);
            v.x = tf32r(v.x); v.y = tf32r(v.y); v.z = tf32r(v.z); v.w = tf32r(v.w);
            *(float4*)(B + SWZ(co * 128 + jg * 16)) = v;
        }
        FENCE_ASYNC();
        __syncthreads();
        if (wid == 0 && elect1()) {
            uint64_t ad = mkdesc(sb + 1024 + bsel * 16384);
            uint64_t bd = mkdesc(sb + 1024 + 32768 + bsel * 8192);
#pragma unroll
            for (int s2 = 0; s2 < 4; s2++)
                mma_tf32(tmem, ad + s2 * 2, bd + s2 * 2, IDESC, (c > 0 || s2 > 0) ? 1u : 0u);
            TC_COMMIT(bsel ? mb1 : mb0);
        }
    }

    MBAR_WAIT(mb0, ph0);
    MBAR_WAIT(mb1, ph1);
    TC_FENCE_AFTER();

    if (wid < 4) {
        const int r = (mt << 2) + wid;
        const int oh = 2 * r + po;
        const int ow = 2 * lid + pw;
#pragma unroll
        for (int cb = 0; cb < 2; cb++) {
            uint32_t d[32];
            LDTM32(d, tmem + cb * 32);
            TC_WAIT_LD();
#pragma unroll
            for (int q = 0; q < 32; q++) {
                int co = cb * 32 + q;
                float v = __uint_as_float(d[q]) + bias[co];
                v = fmaxf(v, 0.f);
                out[(((size_t)n * 64 + co) << 12) + oh * 64 + ow] = v;
            }
        }
    }
    __syncthreads();
    if (wid == 0) TC_DEALLOC(tmem, 128);

#else
    const int m = tid & 127;
    const int half = tid >> 7;
    const int r = (mt << 2) + (m >> 5);
    const int cc = m & 31;
    float acc[32];
#pragma unroll
    for (int j = 0; j < 32; j++) acc[j] = 0.f;
    for (int ci = 0; ci < 128; ci++) {
        const float* ip = inb + (size_t)ci * 1024;
#pragma unroll
        for (int t = 0; t < 4; t++) {
            int i2 = t >> 1, j2 = t & 1;
            int ih = r + po - i2, iw = cc + pw - j2;
            int kh = (1 - po) + 2 * i2, kw = (1 - pw) + 2 * j2;
            float iv = 0.f;
            if (ih >= 0 && ih < 32 && iw >= 0 && iw < 32) iv = fmaxf(ip[ih * 32 + iw], 0.f);
            for (int j = 0; j < 32; j++) {
                int co = half * 32 + j;
                acc[j] = fmaf(iv, Bt[(size_t)co * 2048 + (kh * 4 + kw) * 128 + ci], acc[j]);
            }
        }
    }
    const int oh = 2 * r + po, ow = 2 * cc + pw;
#pragma unroll
    for (int j = 0; j < 32; j++) {
        int co = half * 32 + j;
        float v = fmaxf(acc[j] + bias[co], 0.f);
        out[(((size_t)n * 64 + co) << 12) + oh * 64 + ow] = v;
    }
#endif
}

// ================= VQ via tcgen05 (argmin over -2*v.E + |E|^2) =================
// grid 512 x 256 thr; block handles 128 latents; D = full 512 codes in TMEM.
__global__ void __launch_bounds__(256) vq_tc(
    const float* __restrict__ Ze, const float* __restrict__ E,
    float* __restrict__ Zq, float* __restrict__ counts, float* __restrict__ loss_sum)
{
    const int tid = threadIdx.x;
    extern __shared__ char smem[];
    float* e2s = (float*)(smem + 164864);
    float* red = (float*)(smem + 166912);

#if HAS_TC5
    constexpr uint32_t IDESC = (1u << 4) | (2u << 7) | (2u << 10) | (32u << 17) | (8u << 24);
    const uint32_t sb = smem_u32(smem);
    const uint32_t mb0 = sb + 16;
    char* Ab = smem + 1024;           // 2 chunks x 16KB
    char* Bb = smem + 33792;          // 4 regions (h,g) x 32KB

    const int wid = tid >> 5, lid = tid & 31;
    if (tid == 0) MBAR_INIT(mb0, 1);
    if (wid == 0) { TC_ALLOC(sb, 512); TC_RELINQ(); }
    __syncthreads();
    uint32_t tmem;
    asm volatile("ld.shared.b32 %0, [%1];" : "=r"(tmem) : "r"(sb));

    // stage A: 2 chunks of 128 latents x 32 dims
#pragma unroll
    for (int it = 0; it < 8; it++) {
        int slot = tid + it * 256;
        int g = slot >> 10;
        int jg = (slot >> 7) & 7;
        int m = slot & 127;
        int vi = blockIdx.x * 128 + m;
        int b = vi >> 10, hw = vi & 1023;
        const float* p = Ze + (size_t)b * 65536 + (size_t)(g * 32 + jg * 4) * 1024 + hw;
        float4 v;
        v.x = tf32r(p[0]); v.y = tf32r(p[1024]); v.z = tf32r(p[2048]); v.w = tf32r(p[3072]);
        *(float4*)(Ab + g * 16384 + SWZ(m * 128 + jg * 16)) = v;
    }
    // stage B: 4 regions (h in 0..1 codes, g in 0..1 dims): 256 codes x 32 dims each
#pragma unroll
    for (int it = 0; it < 32; it++) {
        int slot = tid + it * 256;          // 8192 slots
        int reg = slot >> 11;               // (h*2+g)
        int r2 = slot & 2047;
        int row = r2 >> 3, jg = r2 & 7;
        int h = reg >> 1, g = reg & 1;
        float4 v = *(const float4*)(E + (size_t)(h * 256 + row) * 64 + g * 32 + jg * 4);
        v.x = tf32r(v.x); v.y = tf32r(v.y); v.z = tf32r(v.z); v.w = tf32r(v.w);
        *(float4*)(Bb + reg * 32768 + SWZ(row * 128 + jg * 16)) = v;
    }
    // e2s from tf32-rounded E (consistent with MMA dot)
#pragma unroll
    for (int kk = 0; kk < 2; kk++) {
        int k = tid + kk * 256;
        const float4* er = (const float4*)(E + (size_t)k * 64);
        float s = 0.f;
#pragma unroll
        for (int j = 0; j < 16; j++) {
            float4 e = er[j];
            float a = tf32r(e.x), b2 = tf32r(e.y), c2 = tf32r(e.z), d2 = tf32r(e.w);
            s = fmaf(a, a, fmaf(b2, b2, fmaf(c2, c2, fmaf(d2, d2, s))));
        }
        e2s[k] = s;
    }
    FENCE_ASYNC();
    __syncthreads();

    if (wid == 0 && elect1()) {
#pragma unroll
        for (int h = 0; h < 2; h++) {
            uint32_t dt = tmem + h * 256;
#pragma unroll
            for (int g = 0; g < 2; g++) {
                uint64_t ad = mkdesc(sb + 1024 + g * 16384);
                uint64_t bd = mkdesc(sb + 33792 + (h * 2 + g) * 32768);
#pragma unroll
                for (int s2 = 0; s2 < 4; s2++)
                    mma_tf32(dt, ad + s2 * 2, bd + s2 * 2, IDESC, (g > 0 || s2 > 0) ? 1u : 0u);
            }
        }
        TC_COMMIT(mb0);
    }
    __syncthreads();
    MBAR_WAIT(mb0, 0);
    TC_FENCE_AFTER();

    float le = 0.f;
    if (tid < 128) {
        const int row = tid;   // wid 0..3, lane = row's lane
        int bi = 0;
        float best = 3.402823466e38f;
#pragma unroll
        for (int cb = 0; cb < 16; cb++) {
            uint32_t d[32];
            LDTM32(d, tmem + cb * 32);
            TC_WAIT_LD();
#pragma unroll
            for (int q = 0; q < 32; q++) {
                int k = cb * 32 + q;
                float score = e2s[k] - 2.f * __uint_as_float(d[q]);
                if (score < best) { best = score; bi = k; }
            }
        }
        // exact Zq gather + loss with fp32 originals
        int vi = blockIdx.x * 128 + row;
        int b = vi >> 10, hw = vi & 1023;
        const float* zp = Ze + (size_t)b * 65536 + hw;
        float* qp = Zq + (size_t)b * 65536 + hw;
        const float* eb = E + (size_t)bi * 64;
#pragma unroll
        for (int d0 = 0; d0 < 64; d0++) {
            float q = eb[d0];
            float v = zp[(size_t)d0 * 1024];
            qp[(size_t)d0 * 1024] = q;
            float dd = q - v;
            le = fmaf(dd, dd, le);
        }
        atomicAdd(&counts[bi], 1.0f);
    }
    red[tid] = le;
    __syncthreads();
    for (int s = 128; s > 0; s >>= 1) {
        if (tid < s) red[tid] += red[tid + s];
        __syncthreads();
    }
    if (tid == 0) atomicAdd(loss_sum, red[0]);
    __syncthreads();
    if (wid == 0) TC_DEALLOC(tmem, 512);

#else  // ---------- scalar fallback ----------
    const int vi = blockIdx.x * 128 + (tid & 127);
    if (tid < 128) {
        const int b = vi >> 10, hw = vi & 1023;
        const float* zp = Ze + (size_t)b * 65536 + hw;
        float v[64], sv = 0.f;
#pragma unroll
        for (int d = 0; d < 64; d++) { v[d] = zp[(size_t)d * 1024]; sv = fmaf(v[d], v[d], sv); }
        float best = 3.402823466e38f;
        int bi = 0;
        for (int k = 0; k < 512; k++) {
            const float4* er = (const float4*)(E + (size_t)k * 64);
            float dot = 0.f, e2 = 0.f;
#pragma unroll
            for (int j = 0; j < 16; j++) {
                float4 e = er[j];
                dot = fmaf(v[4 * j], e.x, fmaf(v[4 * j + 1], e.y, fmaf(v[4 * j + 2], e.z, fmaf(v[4 * j + 3], e.w, dot))));
                e2 = fmaf(e.x, e.x, fmaf(e.y, e.y, fmaf(e.z, e.z, fmaf(e.w, e.w, e2))));
            }
            float dist = sv + e2 - 2.f * dot;
            if (dist < best) { best = dist; bi = k; }
        }
        float le = 0.f;
        float* qp = Zq + (size_t)b * 65536 + hw;
        const float* eb = E + (size_t)bi * 64;
#pragma unroll
        for (int d = 0; d < 64; d++) {
            float q = eb[d];
            qp[(size_t)d * 1024] = q;
            float dd = q - v[d];
            le = fmaf(dd, dd, le);
        }
        atomicAdd(&counts[bi], 1.0f);
        red[tid] = le;
    } else red[tid] = 0.f;
    __syncthreads();
    for (int s = 128; s > 0; s >>= 1) {
        if (tid < s) red[tid] += red[tid + s];
        __syncthreads();
    }
    if (tid == 0) atomicAdd(loss_sum, red[0]);
#endif
}

// ================= scalar conv (conv1: 4x4 s2 CIN=3) =================
template <int K, int S, int CIN>
__global__ void __launch_bounds__(256) conv_tiled(
    const float* __restrict__ in, const float* __restrict__ w,
    const float* __restrict__ bias, float* __restrict__ out,
    int Cout, int Hin, int Win, int Hout, int Wout, int out_relu)
{
    constexpr int P = 1;
    constexpr int TI = 31 * S + K;
    constexpr int TILE_N = TI * TI;
    constexpr int NS = (TILE_N + 255) / 256;
    constexpr int RW = 3 * S + K;

    __shared__ float tile[TILE_N];
    __shared__ float4 wsm[CIN * K * K];

    const int tid = threadIdx.x;
    const int co0 = blockIdx.x * 4;
    const int n = blockIdx.y;
    const int tilesX = Wout >> 5;
    const int ty = blockIdx.z / tilesX, tx = blockIdx.z % tilesX;
    const int r0 = ty * 32, c0 = tx * 32;

    float* wsm_f = (float*)wsm;
#pragma unroll
    for (int c = 0; c < 4; c++) {
        const float* wp = w + (size_t)(co0 + c) * CIN * K * K;
        for (int j = tid; j < CIN * K * K; j += 256)
            wsm_f[j * 4 + c] = wp[j];
    }

    int goff[NS];
#pragma unroll
    for (int s = 0; s < NS; s++) {
        int i = tid + s * 256;
        goff[s] = -1;
        if (i < TILE_N) {
            int tr = i / TI, tc = i % TI;
            int gr = r0 * S - P + tr, gc = c0 * S - P + tc;
            if (gr >= 0 && gr < Hin && gc >= 0 && gc < Win) goff[s] = gr * Win + gc;
        }
    }

    const int row = tid >> 3;
    const int col4 = (tid & 7) << 2;

    float acc[4][4];
#pragma unroll
    for (int a = 0; a < 4; a++)
#pragma unroll
        for (int b = 0; b < 4; b++) acc[a][b] = 0.f;

    const float* inb = in + (size_t)n * CIN * Hin * Win;

    for (int ci = 0; ci < CIN; ci++) {
        __syncthreads();
        const float* ip = inb + (size_t)ci * Hin * Win;
#pragma unroll
        for (int s = 0; s < NS; s++) {
            int i = tid + s * 256;
            if (i < TILE_N) tile[i] = (goff[s] >= 0) ? ip[goff[s]] : 0.f;
        }
        __syncthreads();

        float rg[K][RW];
#pragma unroll
        for (int a = 0; a < K; a++)
#pragma unroll
            for (int b = 0; b < RW; b++)
                rg[a][b] = tile[(row * S + a) * TI + col4 * S + b];

        const float4* wp = wsm + ci * K * K;
#pragma unroll
        for (int kh = 0; kh < K; kh++)
#pragma unroll
            for (int kw = 0; kw < K; kw++) {
                float4 wv = wp[kh * K + kw];
#pragma unroll
                for (int px = 0; px < 4; px++) {
                    float iv = rg[kh][px * S + kw];
                    acc[px][0] = fmaf(iv, wv.x, acc[px][0]);
                    acc[px][1] = fmaf(iv, wv.y, acc[px][1]);
                    acc[px][2] = fmaf(iv, wv.z, acc[px][2]);
                    acc[px][3] = fmaf(iv, wv.w, acc[px][3]);
                }
            }
    }

#pragma unroll
    for (int c = 0; c < 4; c++) {
        int co = co0 + c;
        float bv = bias ? bias[co] : 0.f;
        size_t base = (((size_t)n * Cout + co) * Hout + r0 + row) * Wout + c0 + col4;
#pragma unroll
        for (int px = 0; px < 4; px++) {
            float v = acc[px][c] + bv;
            if (out_relu) v = fmaxf(v, 0.f);
            out[base + px] = v;
        }
    }
}

// ================= ConvTranspose k=4 s=2 p=1, scalar 4co (tc2) =================
template <int CIN>
__global__ void __launch_bounds__(256) convt421(
    const float* __restrict__ in, const float* __restrict__ w,
    const float* __restrict__ bias, float* __restrict__ out,
    int Cout, int Hin, int Win, int Hout, int Wout, int in_relu, int out_relu)
{
    __shared__ float tile[18 * 18];
    __shared__ float4 wsm[CIN * 16];

    const int tid = threadIdx.x;
    const int co0 = blockIdx.x * 4;
    const int n = blockIdx.y;
    const int tilesX = Wout >> 5;
    const int ty = blockIdx.z / tilesX, tx = blockIdx.z % tilesX;
    const int r0 = ty * 32, c0 = tx * 32;
    const int base_i = (r0 >> 1) - 1, base_j = (c0 >> 1) - 1;

    float* wsm_f = (float*)wsm;
#pragma unroll
    for (int c = 0; c < 4; c++) {
        int co = co0 + c;
        for (int j = tid; j < CIN * 16; j += 256)
            wsm_f[j * 4 + c] =
                (co < Cout) ? w[((size_t)(j >> 4) * Cout + co) * 16 + (j & 15)] : 0.f;
    }

    const int row = tid >> 3;
    const int col4 = (tid & 7) << 2;
    const int oh = r0 + row;
    const int kh_a = (oh + 1) & 1;
    const int ta = ((oh + 1 - kh_a) >> 1) - base_i;
    const int tb = ta - 1;

    float acc[4][4];
#pragma unroll
    for (int a = 0; a < 4; a++)
#pragma unroll
        for (int b = 0; b < 4; b++) acc[a][b] = 0.f;

    const float* inb = in + (size_t)n * CIN * Hin * Win;

    for (int ci = 0; ci < CIN; ci++) {
        __syncthreads();
        for (int i = tid; i < 324; i += 256) {
            int tr = i / 18, tc = i % 18;
            int gi = base_i + tr, gj = base_j + tc;
            float v = 0.f;
            if (gi >= 0 && gi < Hin && gj >= 0 && gj < Win)
                v = inb[((size_t)ci * Hin + gi) * Win + gj];
            if (in_relu) v = fmaxf(v, 0.f);
            tile[i] = v;
        }
        __syncthreads();

        const float4* wp = wsm + ci * 16;
#pragma unroll
        for (int px = 0; px < 4; px++) {
            int ow = c0 + col4 + px;
            int kw_a = (ow + 1) & 1;
            int ja = ((ow + 1 - kw_a) >> 1) - base_j;
            int jb = ja - 1;
            float iaa = tile[ta * 18 + ja], iab = tile[ta * 18 + jb];
            float iba = tile[tb * 18 + ja], ibb = tile[tb * 18 + jb];
            float4 waa = wp[kh_a * 4 + kw_a];
            float4 wab = wp[kh_a * 4 + kw_a + 2];
            float4 wba = wp[(kh_a + 2) * 4 + kw_a];
            float4 wbb = wp[(kh_a + 2) * 4 + kw_a + 2];
            acc[px][0] = fmaf(iaa, waa.x, fmaf(iab, wab.x, fmaf(iba, wba.x, fmaf(ibb, wbb.x, acc[px][0]))));
            acc[px][1] = fmaf(iaa, waa.y, fmaf(iab, wab.y, fmaf(iba, wba.y, fmaf(ibb, wbb.y, acc[px][1]))));
            acc[px][2] = fmaf(iaa, waa.z, fmaf(iab, wab.z, fmaf(iba, wba.z, fmaf(ibb, wbb.z, acc[px][2]))));
            acc[px][3] = fmaf(iaa, waa.w, fmaf(iab, wab.w, fmaf(iba, wba.w, fmaf(ibb, wbb.w, acc[px][3]))));
        }
    }

#pragma unroll
    for (int c = 0; c < 4; c++) {
        int co = co0 + c;
        if (co >= Cout) continue;
        float bv = bias ? bias[co] : 0.f;
        size_t base = (((size_t)n * Cout + co) * Hout + oh) * Wout + c0 + col4;
#pragma unroll
        for (int px = 0; px < 4; px++) {
            float v = acc[px][c] + bv;
            if (out_relu) v = fmaxf(v, 0.f);
            out[base + px] = v;
        }
    }
}

// ================= small kernels =================
__global__ void zero_small(float* counts, float* loss) {
    int t = blockIdx.x * blockDim.x + threadIdx.x;
    if (t < 512) counts[t] = 0.f;
    if (t == 0) loss[0] = 0.f;
}

__global__ void finalize_kernel(const float* __restrict__ counts,
                                const float* __restrict__ loss_sum,
                                float* __restrict__ out, int out_size) {
    __shared__ float red[512];
    int tid = threadIdx.x;
    float c = counts[tid];
    float p = c * (1.0f / 65536.0f);
    red[tid] = p * log2f(p + 1e-10f);
    __syncthreads();
    for (int s = 256; s > 0; s >>= 1) {
        if (tid < s) red[tid] += red[tid + s];
        __syncthreads();
    }
    if (tid == 0) {
        float ent = -red[0];
        float mse = loss_sum[0] * (1.0f / 4194304.0f);
        out[0] = mse + 0.25f * mse;
        out[out_size - 3] = mse;
        out[out_size - 2] = mse;
        out[out_size - 1] = exp2f(ent);
    }
}

// ================= host launcher =================
extern "C" void kernel_launch(void* const* d_in, const int* in_sizes, int n_in,
                              void* d_out, int out_size) {
    const float* x         = (const float*)d_in[0];
    const float* enc_w1    = (const float*)d_in[1];
    const float* enc_b1    = (const float*)d_in[2];
    const float* enc_w2    = (const float*)d_in[3];
    const float* enc_b2    = (const float*)d_in[4];
    const float* enc_w3    = (const float*)d_in[5];
    const float* enc_b3    = (const float*)d_in[6];
    const float* enc_w4    = (const float*)d_in[7];
    const float* enc_b4    = (const float*)d_in[8];
    const float* enc_res_w1= (const float*)d_in[9];
    const float* enc_res_w2= (const float*)d_in[10];
    const float* enc_adj_w = (const float*)d_in[11];
    const float* enc_adj_b = (const float*)d_in[12];
    const float* E         = (const float*)d_in[13];
    const float* dec_adj_w = (const float*)d_in[14];
    const float* dec_adj_b = (const float*)d_in[15];
    const float* dec_res_w1= (const float*)d_in[16];
    const float* dec_res_w2= (const float*)d_in[17];
    const float* tc1_w     = (const float*)d_in[18];
    const float* tc1_b     = (const float*)d_in[19];
    const float* tc2_w     = (const float*)d_in[20];
    const float* tc2_b     = (const float*)d_in[21];
    float* out = (float*)d_out;

    float *b1, *b2, *b3, *b4, *b5, *wt, *cnt, *lsum;
    cudaGetSymbolAddress((void**)&b1, g_buf1);
    cudaGetSymbolAddress((void**)&b2, g_buf2);
    cudaGetSymbolAddress((void**)&b3, g_buf3);
    cudaGetSymbolAddress((void**)&b4, g_buf4);
    cudaGetSymbolAddress((void**)&b5, g_buf5);
    cudaGetSymbolAddress((void**)&wt, g_wt);
    cudaGetSymbolAddress((void**)&cnt, g_counts);
    cudaGetSymbolAddress((void**)&lsum, g_loss);

    cudaFuncSetAttribute(conv_tc<64, 4, 2, 128, 64>, cudaFuncAttributeMaxDynamicSharedMemorySize, 66560);
    cudaFuncSetAttribute(conv_tc<128, 3, 1, 128, 32>, cudaFuncAttributeMaxDynamicSharedMemorySize, 66560);
    cudaFuncSetAttribute(conv_tc<128, 3, 1, 64, 32>, cudaFuncAttributeMaxDynamicSharedMemorySize, 50176);
    cudaFuncSetAttribute(conv_tc<64, 1, 1, 128, 32>, cudaFuncAttributeMaxDynamicSharedMemorySize, 66560);
    cudaFuncSetAttribute(conv_tc<128, 1, 1, 64, 32>, cudaFuncAttributeMaxDynamicSharedMemorySize, 50176);
    cudaFuncSetAttribute(conv_tc<64, 3, 1, 128, 32>, cudaFuncAttributeMaxDynamicSharedMemorySize, 66560);
    cudaFuncSetAttribute(convt_tc, cudaFuncAttributeMaxDynamicSharedMemorySize, 50176);
    cudaFuncSetAttribute(vq_tc, cudaFuncAttributeMaxDynamicSharedMemorySize, 167936);

    // merged weight transpose
    wtrans_all<<<3617, 256>>>(enc_w2, enc_w3, enc_w4, enc_res_w1,
                              dec_adj_w, dec_res_w1, tc1_w, wt);

    const int B = 64;
    dim3 g8(8, B);

    // -------- encoder --------
    conv_tiled<4, 2, 3><<<dim3(16, B, 4), 256>>>(x, enc_w1, enc_b1, b1,
                                                 64, 128, 128, 64, 64, 1);
    conv_tc<64, 4, 2, 128, 64><<<g8, 256, 66560>>>(b1, wt, enc_b2, nullptr, b2, 0, 1);
    conv_tc<128, 3, 1, 128, 32><<<g8, 256, 66560>>>(b2, wt + 131072, enc_b3, nullptr, b3, 0, 1);
    conv_tc<128, 3, 1, 128, 32><<<g8, 256, 66560>>>(b3, wt + 278528, enc_b4, nullptr, b2, 0, 0);
    conv_tc<128, 3, 1, 64, 32><<<g8, 256, 50176>>>(b2, wt + 425984, nullptr, nullptr, b4, 1, 0);
    conv_tc<64, 1, 1, 128, 32><<<g8, 256, 66560>>>(b4, enc_res_w2, nullptr, b2, b3, 1, 0);
    conv_tc<128, 3, 1, 64, 32><<<g8, 256, 50176>>>(b3, wt + 499712, nullptr, nullptr, b4, 1, 0);
    conv_tc<64, 1, 1, 128, 32><<<g8, 256, 66560>>>(b4, enc_res_w2 + 8192, nullptr, b3, b2, 1, 0);
    conv_tc<128, 1, 1, 64, 32><<<g8, 256, 50176>>>(b2, enc_adj_w, enc_adj_b, nullptr, b5, 1, 0);

    // -------- VQ (tensor) --------
    zero_small<<<2, 256>>>(cnt, lsum);
    vq_tc<<<512, 256, 167936>>>(b5, E, b4, cnt, lsum);

    // -------- decoder --------
    conv_tc<64, 3, 1, 128, 32><<<g8, 256, 66560>>>(b4, wt + 573440, dec_adj_b, nullptr, b2, 0, 0);
    conv_tc<128, 3, 1, 64, 32><<<g8, 256, 50176>>>(b2, wt + 647168, nullptr, nullptr, b4, 1, 0);
    conv_tc<64, 1, 1, 128, 32><<<g8, 256, 66560>>>(b4, dec_res_w2, nullptr, b2, b3, 1, 0);
    conv_tc<128, 3, 1, 64, 32><<<g8, 256, 50176>>>(b3, wt + 720896, nullptr, nullptr, b4, 1, 0);
    conv_tc<64, 1, 1, 128, 32><<<g8, 256, 66560>>>(b4, dec_res_w2 + 8192, nullptr, b3, b2, 1, 0);

    convt_tc<<<dim3(8, B, 4), 256, 50176>>>(b2, wt + 794624, tc1_b, b1);
    convt421<64><<<dim3(1, B, 16), 256>>>(b1, tc2_w, tc2_b, out + 1,
                                          3, 64, 64, 128, 128, 0, 0);

    finalize_kernel<<<1, 512>>>(cnt, lsum, out, out_size);
}